// round 2
// baseline (speedup 1.0000x reference)
#include <cuda_runtime.h>
#include <math.h>

// Problem constants (fixed by the dataset instance)
#define BATCH   2
#define SEQ     4608
#define DIM     3584
#define NHD     8
#define DHD     448
#define NPATCH  4096
#define NBOX    12
#define DFF     7168
#define NTOK    24      // BATCH * NBOX
#define TPB     256

// ------------------------- scratch (static device globals) -------------------
__device__ int   g_pos[NTOK];
__device__ int   g_start[BATCH];
__device__ float g_qtok[NTOK * DIM];
__device__ float g_q[NTOK * DIM];
__device__ float g_qk[NTOK * NHD * DIM];            // 688128
__device__ float g_scores[BATCH * NBOX * NHD * NPATCH]; // 786432, reused as attn
__device__ float g_u[NTOK * NHD * DIM];             // 688128
__device__ float g_ctx[NTOK * DIM];
__device__ float g_comb[NTOK * DIM];
__device__ float g_ln[NTOK * DIM];
__device__ float g_hidden[NTOK * DFF];
__device__ float g_rows[NTOK * DIM];
__device__ float g_part[4 * NTOK * DFF];            // split-K partials (688128)

// ------------------------- simple kernels ------------------------------------

__global__ void copy_kernel(const float4* __restrict__ src, float4* __restrict__ dst, long n4) {
    long i = (long)blockIdx.x * blockDim.x + threadIdx.x;
    long stride = (long)gridDim.x * blockDim.x;
    for (; i < n4; i += stride) dst[i] = src[i];
}

// find first NBOX box-end positions per batch (in order) + first image-mask index.
// image_mask dtype is unknown (bool may arrive as int8/uint8, int32, or float32);
// detect element layout from the raw bytes of batch 0 (safe: buffer >= B*S bytes).
__global__ void scan_kernel(const int* __restrict__ ids,
                            const unsigned char* __restrict__ mask,
                            const int* __restrict__ tokPtr) {
    int b = blockIdx.x;
    __shared__ int sh[SEQ];
    __shared__ int s_f0;
    __shared__ int s_es, s_off;
    __shared__ int s_first;
    int tid = threadIdx.x;

    // ---- detect mask element size (1 or 4 bytes) + value-byte offset ----
    if (tid == 0) s_f0 = 0x7fffffff;
    __syncthreads();
    for (int i = tid; i < SEQ; i += blockDim.x) {
        if (mask[i] != 0) { atomicMin(&s_f0, i); break; }
    }
    __syncthreads();
    if (tid == 0) {
        int f0 = s_f0;
        unsigned char b0 = mask[f0];
        unsigned char b1 = mask[f0 + 1];
        if (b0 == 1u && b1 == 0u)      { s_es = 4; s_off = 0; }  // int32 ones
        else if (b0 == 0x80u)          { s_es = 4; s_off = 2; }  // float32 1.0f
        else                           { s_es = 1; s_off = 0; }  // byte/bool
        s_first = SEQ;
    }
    __syncthreads();
    int es = s_es, off = s_off;

    // ---- first true element of this batch's mask row ----
    for (int i = tid; i < SEQ; i += blockDim.x) {
        if (mask[((long)b * SEQ + i) * es + off] != 0) atomicMin(&s_first, i);
    }
    __syncthreads();
    if (tid == 0) g_start[b] = s_first;

    // ---- box-end token positions (ids are int32) ----
    for (int i = tid; i < SEQ; i += blockDim.x)
        sh[i] = ids[(long)b * SEQ + i];
    __syncthreads();
    if (tid < 32) {
        int tok = *tokPtr;
        int count = 0;
        for (int base = 0; base < SEQ && count < NBOX; base += 32) {
            unsigned bal = __ballot_sync(0xffffffffu, sh[base + tid] == tok);
            while (bal && count < NBOX) {
                int o = __ffs(bal) - 1;
                if (tid == 0) g_pos[b * NBOX + count] = base + o;
                count++;
                bal &= bal - 1;
            }
        }
    }
}

__global__ void gather_kernel(const float* __restrict__ emb) {
    int r = blockIdx.x;              // 0..23
    int b = r / NBOX;
    const float* src = emb + ((long)b * SEQ + g_pos[r]) * DIM;
    for (int i = threadIdx.x; i < DIM; i += blockDim.x) g_qtok[(long)r * DIM + i] = src[i];
}

__global__ void scatter_kernel(float* __restrict__ out) {
    int r = blockIdx.x;
    int b = r / NBOX;
    float* dst = out + ((long)b * SEQ + g_pos[r]) * DIM;
    for (int i = threadIdx.x; i < DIM; i += blockDim.x) dst[i] = g_rows[(long)r * DIM + i];
}

// ------------------------- GEMM (register tiled, optional split-K) -----------
// C[m,n] = sum_k A[m,k] * (TB ? B[n,k] : B[k,n]); M must equal BM.
template<int BM, int BN, int BK, int TM, int TN, bool TB, int SK>
__global__ __launch_bounds__(TPB) void gemm_kernel(
    const float* __restrict__ A, int lda, long Az,
    const float* __restrict__ B, int ldb, long Bz,
    float* __restrict__ C, int ldc, long Cz,   // when SK>1: C is the partial buffer
    int M, int N, int K,
    const float* __restrict__ bias, long biasZ,
    const float* __restrict__ resid, long residZ,
    float scale, int act,
    const int* __restrict__ patchStart)
{
    const int z  = blockIdx.z;
    const int n0 = blockIdx.x * BN;
    const int s  = blockIdx.y;
    const int kLen = K / SK;
    const int kBeg = s * kLen;

    A += (long)z * Az;
    B += (long)z * Bz;
    if (patchStart) B += (long)patchStart[z] * ldb;

    __shared__ float a_sm[BK][BM];
    __shared__ float b_sm[BK][BN];

    float acc[TM][TN];
#pragma unroll
    for (int i = 0; i < TM; i++)
#pragma unroll
        for (int j = 0; j < TN; j++) acc[i][j] = 0.f;

    const int tid = threadIdx.x;
    constexpr int NTX = BN / TN;
    const int tx = tid % NTX;
    const int ty = tid / NTX;

    for (int k0 = kBeg; k0 < kBeg + kLen; k0 += BK) {
        // load A tile (transposed into smem), float4 along K
#pragma unroll
        for (int i = tid; i < BM * BK / 4; i += TPB) {
            int mm = i / (BK / 4);
            int kc = i % (BK / 4);
            float4 v = *reinterpret_cast<const float4*>(A + (long)mm * lda + k0 + kc * 4);
            a_sm[kc * 4 + 0][mm] = v.x;
            a_sm[kc * 4 + 1][mm] = v.y;
            a_sm[kc * 4 + 2][mm] = v.z;
            a_sm[kc * 4 + 3][mm] = v.w;
        }
        if (TB) {
#pragma unroll
            for (int i = tid; i < BN * BK / 4; i += TPB) {
                int nn = i / (BK / 4);
                int kc = i % (BK / 4);
                float4 v = *reinterpret_cast<const float4*>(B + (long)(n0 + nn) * ldb + k0 + kc * 4);
                b_sm[kc * 4 + 0][nn] = v.x;
                b_sm[kc * 4 + 1][nn] = v.y;
                b_sm[kc * 4 + 2][nn] = v.z;
                b_sm[kc * 4 + 3][nn] = v.w;
            }
        } else {
#pragma unroll
            for (int i = tid; i < BK * BN / 4; i += TPB) {
                int kk = i / (BN / 4);
                int nc = i % (BN / 4);
                float4 v = *reinterpret_cast<const float4*>(B + (long)(k0 + kk) * ldb + n0 + nc * 4);
                *reinterpret_cast<float4*>(&b_sm[kk][nc * 4]) = v;
            }
        }
        __syncthreads();
#pragma unroll
        for (int kk = 0; kk < BK; kk++) {
            float af[TM], bf[TN];
#pragma unroll
            for (int i = 0; i < TM; i++) af[i] = a_sm[kk][ty * TM + i];
#pragma unroll
            for (int j = 0; j < TN; j++) bf[j] = b_sm[kk][tx * TN + j];
#pragma unroll
            for (int i = 0; i < TM; i++)
#pragma unroll
                for (int j = 0; j < TN; j++) acc[i][j] = fmaf(af[i], bf[j], acc[i][j]);
        }
        __syncthreads();
    }

    if (SK > 1) {
#pragma unroll
        for (int i = 0; i < TM; i++) {
            int m = ty * TM + i;
#pragma unroll
            for (int j = 0; j < TN; j++) {
                int n = n0 + tx * TN + j;
                C[((long)(z * SK + s) * M + m) * N + n] = acc[i][j];
            }
        }
    } else {
#pragma unroll
        for (int i = 0; i < TM; i++) {
            int m = ty * TM + i;
#pragma unroll
            for (int j = 0; j < TN; j++) {
                int n = n0 + tx * TN + j;
                float v = acc[i][j];
                if (bias)  v += bias[z * biasZ + n];
                v *= scale;
                if (act)   v = v * normcdff(v);
                if (resid) v += resid[z * residZ + (long)m * ldc + n];
                C[z * Cz + (long)m * ldc + n] = v;
            }
        }
    }
}

// reduce split-K partials + epilogue
__global__ void combine_kernel(const float* __restrict__ P, int SK,
                               float* __restrict__ C, int ldc, long Cz, int M, int N,
                               const float* __restrict__ bias, long biasZ,
                               const float* __restrict__ resid, long residZ,
                               float scale, int act, int total) {
    int idx = blockIdx.x * blockDim.x + threadIdx.x;
    if (idx >= total) return;
    int n = idx % N;
    int t = idx / N;
    int m = t % M;
    int z = t / M;
    float v = 0.f;
    for (int s = 0; s < SK; s++) v += P[((long)(z * SK + s) * M + m) * N + n];
    if (bias)  v += bias[z * biasZ + n];
    v *= scale;
    if (act)   v = v * normcdff(v);
    if (resid) v += resid[z * residZ + (long)m * ldc + n];
    C[z * Cz + (long)m * ldc + n] = v;
}

// ------------------------- masked softmax over patches ------------------------
__global__ void softmax_kernel(float* __restrict__ scores,
                               const float* __restrict__ boxes,
                               const int* __restrict__ thw) {
    int blk = blockIdx.x;            // (b*12+n)*8 + h
    int b = blk / (NBOX * NHD);
    int n = (blk / NHD) % NBOX;
    int hg = thw[1], wg = thw[2];
    const float* bx = boxes + (long)(b * NBOX + n) * 4;
    float x1 = bx[0], y1 = bx[1], x2 = bx[2], y2 = bx[3];
    int px1 = min(max((int)floorf(x1 * (float)wg), 0), wg - 1);
    int px2 = max(px1 + 1, min((int)floorf(x2 * (float)wg), wg));
    int py1 = min(max((int)floorf(y1 * (float)hg), 0), hg - 1);
    int py2 = max(py1 + 1, min((int)floorf(y2 * (float)hg), hg));

    float* row = scores + (long)blk * NPATCH;
    __shared__ float sh[NPATCH];
    __shared__ float red[TPB];
    int tid = threadIdx.x;
    int hw = hg * wg;

    float mx = -1e30f;
    for (int i = tid; i < NPATCH; i += TPB) {
        int q = i % hw;
        int rr = q / wg, cc = q % wg;
        bool in = (rr >= py1) && (rr < py2) && (cc >= px1) && (cc < px2);
        float v = in ? row[i] : -1e30f;
        sh[i] = v;
        mx = fmaxf(mx, v);
    }
    red[tid] = mx;
    __syncthreads();
    for (int s = TPB / 2; s > 0; s >>= 1) {
        if (tid < s) red[tid] = fmaxf(red[tid], red[tid + s]);
        __syncthreads();
    }
    float maxv = red[0];
    __syncthreads();

    float sum = 0.f;
    for (int i = tid; i < NPATCH; i += TPB) {
        float e = expf(sh[i] - maxv);   // masked entries underflow to exactly 0
        sh[i] = e;
        sum += e;
    }
    red[tid] = sum;
    __syncthreads();
    for (int s = TPB / 2; s > 0; s >>= 1) {
        if (tid < s) red[tid] += red[tid + s];
        __syncthreads();
    }
    float inv = 1.f / red[0];
    __syncthreads();
    for (int i = tid; i < NPATCH; i += TPB) row[i] = sh[i] * inv;
}

// ------------------------- layernorm ------------------------------------------
__global__ void ln_kernel(const float* __restrict__ gamma, const float* __restrict__ beta) {
    int r = blockIdx.x;
    const float* x = g_comb + (long)r * DIM;
    __shared__ float red[TPB];
    __shared__ float red2[TPB];
    int tid = threadIdx.x;
    float s = 0.f, s2 = 0.f;
    for (int i = tid; i < DIM; i += TPB) {
        float v = x[i];
        s += v;
        s2 += v * v;
    }
    red[tid] = s; red2[tid] = s2;
    __syncthreads();
    for (int st = TPB / 2; st > 0; st >>= 1) {
        if (tid < st) { red[tid] += red[tid + st]; red2[tid] += red2[tid + st]; }
        __syncthreads();
    }
    float mu = red[0] / DIM;
    float var = red2[0] / DIM - mu * mu;
    float inv = rsqrtf(var + 1e-5f);
    for (int i = tid; i < DIM; i += TPB)
        g_ln[(long)r * DIM + i] = (x[i] - mu) * inv * gamma[i] + beta[i];
}

// ------------------------- launch ---------------------------------------------
extern "C" void kernel_launch(void* const* d_in, const int* in_sizes, int n_in,
                              void* d_out, int out_size) {
    const float*         emb   = (const float*)d_in[0];
    const int*           ids   = (const int*)d_in[1];
    const unsigned char* msk   = (const unsigned char*)d_in[2];
    const float*         boxes = (const float*)d_in[3];
    const int*           thw   = (const int*)d_in[4];
    const int*           tok   = (const int*)d_in[5];
    const float*         Win   = (const float*)d_in[6];   // [3D, D]
    const float*         bin   = (const float*)d_in[7];
    const float*         Wout  = (const float*)d_in[8];
    const float*         bout  = (const float*)d_in[9];
    const float*         gam   = (const float*)d_in[10];
    const float*         bet   = (const float*)d_in[11];
    const float*         W1    = (const float*)d_in[12];  // [2D, D]
    const float*         b1    = (const float*)d_in[13];
    const float*         W2    = (const float*)d_in[14];  // [D, 2D]
    const float*         b2    = (const float*)d_in[15];
    float*               out   = (float*)d_out;

    const float* Wq = Win;
    const float* Wk = Win + (long)DIM * DIM;
    const float* Wv = Win + 2L * DIM * DIM;
    const float* bv = bin + 2L * DIM;

    float *qtok, *q, *qk, *scores, *u, *ctx, *comb, *ln, *hidden, *rows, *part;
    int *pos, *start;
    cudaGetSymbolAddress((void**)&qtok,   g_qtok);
    cudaGetSymbolAddress((void**)&q,      g_q);
    cudaGetSymbolAddress((void**)&qk,     g_qk);
    cudaGetSymbolAddress((void**)&scores, g_scores);
    cudaGetSymbolAddress((void**)&u,      g_u);
    cudaGetSymbolAddress((void**)&ctx,    g_ctx);
    cudaGetSymbolAddress((void**)&comb,   g_comb);
    cudaGetSymbolAddress((void**)&ln,     g_ln);
    cudaGetSymbolAddress((void**)&hidden, g_hidden);
    cudaGetSymbolAddress((void**)&rows,   g_rows);
    cudaGetSymbolAddress((void**)&part,   g_part);
    cudaGetSymbolAddress((void**)&pos,    g_pos);
    cudaGetSymbolAddress((void**)&start,  g_start);

    const float scale = 1.0f / sqrtf((float)DHD);
    const long n4 = (long)BATCH * SEQ * DIM / 4;

    // 1. output base copy
    copy_kernel<<<8192, TPB>>>((const float4*)emb, (float4*)out, n4);
    // 2. positions + patch start (mask dtype auto-detected)
    scan_kernel<<<BATCH, TPB>>>(ids, msk, tok);
    // 3. gather query tokens
    gather_kernel<<<NTOK, TPB>>>(emb);
    // 4. q = (qtok @ Wq^T + bq) * scale     [24,3584]  (split-K 4)
    gemm_kernel<24, 64, 32, 3, 2, true, 4><<<dim3(DIM / 64, 4, 1), TPB>>>(
        qtok, DIM, 0, Wq, DIM, 0, part, 0, 0, NTOK, DIM, DIM,
        nullptr, 0, nullptr, 0, 1.f, 0, nullptr);
    combine_kernel<<<(NTOK * DIM + TPB - 1) / TPB, TPB>>>(
        part, 4, q, DIM, 0, NTOK, DIM, bin, 0, nullptr, 0, scale, 0, NTOK * DIM);
    // 5. qk[bn,h,:] = Wk_h^T q[bn,h,:]      (NN per head, z=8)
    gemm_kernel<24, 64, 32, 3, 2, false, 1><<<dim3(DIM / 64, 1, NHD), TPB>>>(
        q + 0, DIM, DHD, Wk, DIM, (long)DHD * DIM,
        qk, NHD * DIM, DIM, NTOK, DIM, DHD,
        nullptr, 0, nullptr, 0, 1.f, 0, nullptr);
    // 6. scores = qk @ patches^T            (NT per batch, M=96)
    gemm_kernel<96, 64, 32, 6, 4, true, 1><<<dim3(NPATCH / 64, 1, BATCH), TPB>>>(
        qk, DIM, (long)NBOX * NHD * DIM,
        emb, DIM, (long)SEQ * DIM,
        scores, NPATCH, (long)NBOX * NHD * NPATCH,
        NBOX * NHD, NPATCH, DIM,
        nullptr, 0, nullptr, 0, 1.f, 0, start);
    // 7. masked softmax (in place -> attn)
    softmax_kernel<<<BATCH * NBOX * NHD, TPB>>>(scores, boxes, thw);
    // 8. u = attn @ patches                  (NN per batch, M=96)
    gemm_kernel<96, 64, 32, 6, 4, false, 1><<<dim3(DIM / 64, 1, BATCH), TPB>>>(
        scores, NPATCH, (long)NBOX * NHD * NPATCH,
        emb, DIM, (long)SEQ * DIM,
        u, DIM, (long)NBOX * NHD * DIM,
        NBOX * NHD, DIM, NPATCH,
        nullptr, 0, nullptr, 0, 1.f, 0, start);
    // 9. ctx[:, h*448:] = u_h @ Wv_h^T + bv_h  (NT per head, split-K 4)
    gemm_kernel<24, 64, 32, 3, 2, true, 4><<<dim3(DHD / 64, 4, NHD), TPB>>>(
        u, NHD * DIM, DIM, Wv, DIM, (long)DHD * DIM,
        part, 0, 0, NTOK, DHD, DIM,
        nullptr, 0, nullptr, 0, 1.f, 0, nullptr);
    combine_kernel<<<(NHD * NTOK * DHD + TPB - 1) / TPB, TPB>>>(
        part, 4, ctx, DIM, DHD, NTOK, DHD, bv, DHD, nullptr, 0, 1.f, 0, NHD * NTOK * DHD);
    // 10. combined = ctx @ Wout^T + bout + qtok   (split-K 4)
    gemm_kernel<24, 64, 32, 3, 2, true, 4><<<dim3(DIM / 64, 4, 1), TPB>>>(
        ctx, DIM, 0, Wout, DIM, 0, part, 0, 0, NTOK, DIM, DIM,
        nullptr, 0, nullptr, 0, 1.f, 0, nullptr);
    combine_kernel<<<(NTOK * DIM + TPB - 1) / TPB, TPB>>>(
        part, 4, comb, DIM, 0, NTOK, DIM, bout, 0, qtok, 0, 1.f, 0, NTOK * DIM);
    // 11. layernorm
    ln_kernel<<<NTOK, TPB>>>(gam, bet);
    // 12. hidden = gelu(ln @ W1^T + b1)           (split-K 4)
    gemm_kernel<24, 64, 32, 3, 2, true, 4><<<dim3(DFF / 64, 4, 1), TPB>>>(
        ln, DIM, 0, W1, DIM, 0, part, 0, 0, NTOK, DFF, DIM,
        nullptr, 0, nullptr, 0, 1.f, 0, nullptr);
    combine_kernel<<<(NTOK * DFF + TPB - 1) / TPB, TPB>>>(
        part, 4, hidden, DFF, 0, NTOK, DFF, b1, 0, nullptr, 0, 1.f, 1, NTOK * DFF);
    // 13. rows = ln + hidden @ W2^T + b2          (split-K 4)
    gemm_kernel<24, 64, 32, 3, 2, true, 4><<<dim3(DIM / 64, 4, 1), TPB>>>(
        hidden, DFF, 0, W2, DFF, 0, part, 0, 0, NTOK, DIM, DFF,
        nullptr, 0, nullptr, 0, 1.f, 0, nullptr);
    combine_kernel<<<(NTOK * DIM + TPB - 1) / TPB, TPB>>>(
        part, 4, rows, DIM, 0, NTOK, DIM, b2, 0, ln, 0, 1.f, 0, NTOK * DIM);
    // 14. scatter the 24 rows
    scatter_kernel<<<NTOK, TPB>>>(out);
}

// round 3
// speedup vs baseline: 1.3037x; 1.3037x over previous
#include <cuda_runtime.h>
#include <math.h>

#define BATCH   2
#define SEQ     4608
#define DIM     3584
#define NHD     8
#define DHD     448
#define NPATCH  4096
#define NBOX    12
#define DFF     7168
#define NTOK    24
#define TPB     256
#define KCMAX   448

// ------------------------- scratch ------------------------------------------
__device__ int   g_pos[NTOK];
__device__ int   g_start[BATCH];
__device__ float g_qtok[NTOK * DIM];
__device__ float g_q[NTOK * DIM];
__device__ float g_qk[NTOK * NHD * DIM];
__device__ float g_scores[BATCH * NBOX * NHD * NPATCH];
__device__ float g_u[NTOK * NHD * DIM];
__device__ float g_ctx[NTOK * DIM];
__device__ float g_comb[NTOK * DIM];
__device__ float g_ln[NTOK * DIM];
__device__ float g_hidden[NTOK * DFF];
__device__ float g_rows[NTOK * DIM];
__device__ float g_part[5505024];          // max split-K partial (22 MB)

// ------------------------- simple kernels ------------------------------------
__global__ void copy_kernel(const float4* __restrict__ src, float4* __restrict__ dst, long n4) {
    long i = (long)blockIdx.x * blockDim.x + threadIdx.x;
    long stride = (long)gridDim.x * blockDim.x;
    for (; i < n4; i += stride) dst[i] = src[i];
}

__global__ void scan_kernel(const int* __restrict__ ids,
                            const unsigned char* __restrict__ mask,
                            const int* __restrict__ tokPtr) {
    int b = blockIdx.x;
    __shared__ int sh[SEQ];
    __shared__ int s_f0, s_es, s_off, s_first;
    int tid = threadIdx.x;

    if (tid == 0) s_f0 = 0x7fffffff;
    __syncthreads();
    for (int i = tid; i < SEQ; i += blockDim.x) {
        if (mask[i] != 0) { atomicMin(&s_f0, i); break; }
    }
    __syncthreads();
    if (tid == 0) {
        int f0 = s_f0;
        unsigned char b0 = mask[f0];
        unsigned char b1 = mask[f0 + 1];
        if (b0 == 1u && b1 == 0u)      { s_es = 4; s_off = 0; }
        else if (b0 == 0x80u)          { s_es = 4; s_off = 2; }
        else                           { s_es = 1; s_off = 0; }
        s_first = SEQ;
    }
    __syncthreads();
    int es = s_es, off = s_off;
    for (int i = tid; i < SEQ; i += blockDim.x)
        if (mask[((long)b * SEQ + i) * es + off] != 0) atomicMin(&s_first, i);
    __syncthreads();
    if (tid == 0) g_start[b] = s_first;

    for (int i = tid; i < SEQ; i += blockDim.x)
        sh[i] = ids[(long)b * SEQ + i];
    __syncthreads();
    if (tid < 32) {
        int tok = *tokPtr;
        int count = 0;
        for (int base = 0; base < SEQ && count < NBOX; base += 32) {
            unsigned bal = __ballot_sync(0xffffffffu, sh[base + tid] == tok);
            while (bal && count < NBOX) {
                int o = __ffs(bal) - 1;
                if (tid == 0) g_pos[b * NBOX + count] = base + o;
                count++;
                bal &= bal - 1;
            }
        }
    }
}

__global__ void gather_kernel(const float* __restrict__ emb) {
    int r = blockIdx.x;
    int b = r / NBOX;
    const float* src = emb + ((long)b * SEQ + g_pos[r]) * DIM;
    for (int i = threadIdx.x; i < DIM; i += blockDim.x) g_qtok[(long)r * DIM + i] = src[i];
}

__global__ void scatter_kernel(float* __restrict__ out) {
    int r = blockIdx.x;
    int b = r / NBOX;
    float* dst = out + ((long)b * SEQ + g_pos[r]) * DIM;
    for (int i = threadIdx.x; i < DIM; i += blockDim.x) dst[i] = g_rows[(long)r * DIM + i];
}

// ------------------------- streamed skinny GEMM (TB): C[24,N]=A[24,K]@W[N,K]^T
// A chunk in smem (broadcast reads), W streamed from gmem, 2 rows/thread.
// Writes split-K partials P[((z*SK+s)*24+m)*N+n].
__global__ __launch_bounds__(TPB) void skinny_tb(
    const float* __restrict__ A, int lda, long Az,
    const float* __restrict__ W, int ldw, long Wz,
    float* __restrict__ P, int N, int K, int SK)
{
    const int z = blockIdx.z, s = blockIdx.y;
    const int n0 = blockIdx.x * 512;
    const int Kc = K / SK;
    const int kBeg = s * Kc;
    A += (long)z * Az;
    W += (long)z * Wz;

    __shared__ float a_sm[NTOK * KCMAX];
    const int tid = threadIdx.x;
    for (int i = tid; i < NTOK * Kc; i += TPB) {
        int m = i / Kc, k = i % Kc;
        a_sm[m * Kc + k] = A[(long)m * lda + kBeg + k];
    }
    __syncthreads();

    const int n1 = n0 + tid;
    const int n2 = n0 + 256 + tid;
    const bool v1 = n1 < N, v2 = n2 < N;
    const float* w1p = W + (long)n1 * ldw + kBeg;
    const float* w2p = W + (long)n2 * ldw + kBeg;

    float acc0[NTOK], acc1[NTOK];
#pragma unroll
    for (int m = 0; m < NTOK; m++) { acc0[m] = 0.f; acc1[m] = 0.f; }

    for (int k = 0; k < Kc; k += 4) {
        float4 w0 = v1 ? *reinterpret_cast<const float4*>(w1p + k) : make_float4(0, 0, 0, 0);
        float4 w1 = v2 ? *reinterpret_cast<const float4*>(w2p + k) : make_float4(0, 0, 0, 0);
#pragma unroll
        for (int m = 0; m < NTOK; m++) {
            float4 a = *reinterpret_cast<const float4*>(&a_sm[m * Kc + k]);
            acc0[m] = fmaf(a.x, w0.x, acc0[m]);
            acc0[m] = fmaf(a.y, w0.y, acc0[m]);
            acc0[m] = fmaf(a.z, w0.z, acc0[m]);
            acc0[m] = fmaf(a.w, w0.w, acc0[m]);
            acc1[m] = fmaf(a.x, w1.x, acc1[m]);
            acc1[m] = fmaf(a.y, w1.y, acc1[m]);
            acc1[m] = fmaf(a.z, w1.z, acc1[m]);
            acc1[m] = fmaf(a.w, w1.w, acc1[m]);
        }
    }
    long base = ((long)(z * SK + s) * NTOK) * N;
#pragma unroll
    for (int m = 0; m < NTOK; m++) {
        if (v1) P[base + (long)m * N + n1] = acc0[m];
        if (v2) P[base + (long)m * N + n2] = acc1[m];
    }
}

// streamed skinny GEMM (NN): C[24,N]=A[24,K]@B[K,N]; B contiguous along n.
__global__ __launch_bounds__(TPB) void skinny_nn(
    const float* __restrict__ A, int lda, long Az,
    const float* __restrict__ W, int ldw, long Wz,
    float* __restrict__ P, int N, int K, int SK)
{
    const int z = blockIdx.z, s = blockIdx.y;
    const int n0 = blockIdx.x * 1024;
    const int Kc = K / SK;
    const int kBeg = s * Kc;
    A += (long)z * Az;
    W += (long)z * Wz;

    __shared__ float a_sm[NTOK * 112];
    const int tid = threadIdx.x;
    for (int i = tid; i < NTOK * Kc; i += TPB) {
        int m = i / Kc, k = i % Kc;
        a_sm[m * Kc + k] = A[(long)m * lda + kBeg + k];
    }
    __syncthreads();

    const int n = n0 + tid * 4;
    if (n >= N) return;
    float4 acc[NTOK];
#pragma unroll
    for (int m = 0; m < NTOK; m++) acc[m] = make_float4(0, 0, 0, 0);

    for (int k = 0; k < Kc; k++) {
        float4 w = *reinterpret_cast<const float4*>(W + (long)(kBeg + k) * ldw + n);
#pragma unroll
        for (int m = 0; m < NTOK; m++) {
            float a = a_sm[m * Kc + k];
            acc[m].x = fmaf(a, w.x, acc[m].x);
            acc[m].y = fmaf(a, w.y, acc[m].y);
            acc[m].z = fmaf(a, w.z, acc[m].z);
            acc[m].w = fmaf(a, w.w, acc[m].w);
        }
    }
    long base = ((long)(z * SK + s) * NTOK) * N;
#pragma unroll
    for (int m = 0; m < NTOK; m++)
        *reinterpret_cast<float4*>(&P[base + (long)m * N + n]) = acc[m];
}

// ------------------------- big GEMM (register tiled, split-K partials) -------
template<int BM, int BN, int BK, int TM, int TN, bool TB, int SK>
__global__ __launch_bounds__(TPB) void gemm_kernel(
    const float* __restrict__ A, int lda, long Az,
    const float* __restrict__ B, int ldb, long Bz,
    float* __restrict__ C, int ldc, long Cz,
    int M, int N, int K,
    const int* __restrict__ patchStart)
{
    const int z  = blockIdx.z;
    const int n0 = blockIdx.x * BN;
    const int s  = blockIdx.y;
    const int kLen = K / SK;
    const int kBeg = s * kLen;

    A += (long)z * Az;
    B += (long)z * Bz;
    if (patchStart) B += (long)patchStart[z] * ldb;

    __shared__ float a_sm[BK][BM];
    __shared__ float b_sm[BK][BN];

    float acc[TM][TN];
#pragma unroll
    for (int i = 0; i < TM; i++)
#pragma unroll
        for (int j = 0; j < TN; j++) acc[i][j] = 0.f;

    const int tid = threadIdx.x;
    constexpr int NTX = BN / TN;
    const int tx = tid % NTX;
    const int ty = tid / NTX;

    for (int k0 = kBeg; k0 < kBeg + kLen; k0 += BK) {
#pragma unroll
        for (int i = tid; i < BM * BK / 4; i += TPB) {
            int mm = i / (BK / 4);
            int kc = i % (BK / 4);
            float4 v = *reinterpret_cast<const float4*>(A + (long)mm * lda + k0 + kc * 4);
            a_sm[kc * 4 + 0][mm] = v.x;
            a_sm[kc * 4 + 1][mm] = v.y;
            a_sm[kc * 4 + 2][mm] = v.z;
            a_sm[kc * 4 + 3][mm] = v.w;
        }
        if (TB) {
#pragma unroll
            for (int i = tid; i < BN * BK / 4; i += TPB) {
                int nn = i / (BK / 4);
                int kc = i % (BK / 4);
                float4 v = *reinterpret_cast<const float4*>(B + (long)(n0 + nn) * ldb + k0 + kc * 4);
                b_sm[kc * 4 + 0][nn] = v.x;
                b_sm[kc * 4 + 1][nn] = v.y;
                b_sm[kc * 4 + 2][nn] = v.z;
                b_sm[kc * 4 + 3][nn] = v.w;
            }
        } else {
#pragma unroll
            for (int i = tid; i < BK * BN / 4; i += TPB) {
                int kk = i / (BN / 4);
                int nc = i % (BN / 4);
                float4 v = *reinterpret_cast<const float4*>(B + (long)(k0 + kk) * ldb + n0 + nc * 4);
                *reinterpret_cast<float4*>(&b_sm[kk][nc * 4]) = v;
            }
        }
        __syncthreads();
#pragma unroll
        for (int kk = 0; kk < BK; kk++) {
            float af[TM], bf[TN];
#pragma unroll
            for (int i = 0; i < TM; i++) af[i] = a_sm[kk][ty * TM + i];
#pragma unroll
            for (int j = 0; j < TN; j++) bf[j] = b_sm[kk][tx * TN + j];
#pragma unroll
            for (int i = 0; i < TM; i++)
#pragma unroll
                for (int j = 0; j < TN; j++) acc[i][j] = fmaf(af[i], bf[j], acc[i][j]);
        }
        __syncthreads();
    }

#pragma unroll
    for (int i = 0; i < TM; i++) {
        int m = ty * TM + i;
#pragma unroll
        for (int j = 0; j < TN; j++) {
            int n = n0 + tx * TN + j;
            C[((long)(z * SK + s) * M + m) * N + n] = acc[i][j];
        }
    }
}

// reduce split-K partials + epilogue
__global__ void combine_kernel(const float* __restrict__ P, int SK,
                               float* __restrict__ C, int ldc, long Cz, int M, int N,
                               const float* __restrict__ bias, long biasZ,
                               const float* __restrict__ resid, long residZ,
                               float scale, int act, int total) {
    int idx = blockIdx.x * blockDim.x + threadIdx.x;
    if (idx >= total) return;
    int n = idx % N;
    int t = idx / N;
    int m = t % M;
    int z = t / M;
    float v = 0.f;
    for (int s = 0; s < SK; s++) v += P[((long)(z * SK + s) * M + m) * N + n];
    if (bias)  v += bias[z * biasZ + n];
    v *= scale;
    if (act)   v = v * normcdff(v);
    if (resid) v += resid[z * residZ + (long)m * ldc + n];
    C[z * Cz + (long)m * ldc + n] = v;
}

// ------------------------- masked softmax ------------------------------------
__global__ void softmax_kernel(float* __restrict__ scores,
                               const float* __restrict__ boxes,
                               const int* __restrict__ thw) {
    int blk = blockIdx.x;
    int b = blk / (NBOX * NHD);
    int n = (blk / NHD) % NBOX;
    int hg = thw[1], wg = thw[2];
    const float* bx = boxes + (long)(b * NBOX + n) * 4;
    float x1 = bx[0], y1 = bx[1], x2 = bx[2], y2 = bx[3];
    int px1 = min(max((int)floorf(x1 * (float)wg), 0), wg - 1);
    int px2 = max(px1 + 1, min((int)floorf(x2 * (float)wg), wg));
    int py1 = min(max((int)floorf(y1 * (float)hg), 0), hg - 1);
    int py2 = max(py1 + 1, min((int)floorf(y2 * (float)hg), hg));

    float* row = scores + (long)blk * NPATCH;
    __shared__ float sh[NPATCH];
    __shared__ float red[TPB];
    int tid = threadIdx.x;
    int hw = hg * wg;

    float mx = -1e30f;
    for (int i = tid; i < NPATCH; i += TPB) {
        int q = i % hw;
        int rr = q / wg, cc = q % wg;
        bool in = (rr >= py1) && (rr < py2) && (cc >= px1) && (cc < px2);
        float v = in ? row[i] : -1e30f;
        sh[i] = v;
        mx = fmaxf(mx, v);
    }
    red[tid] = mx;
    __syncthreads();
    for (int s = TPB / 2; s > 0; s >>= 1) {
        if (tid < s) red[tid] = fmaxf(red[tid], red[tid + s]);
        __syncthreads();
    }
    float maxv = red[0];
    __syncthreads();

    float sum = 0.f;
    for (int i = tid; i < NPATCH; i += TPB) {
        float e = expf(sh[i] - maxv);
        sh[i] = e;
        sum += e;
    }
    red[tid] = sum;
    __syncthreads();
    for (int s = TPB / 2; s > 0; s >>= 1) {
        if (tid < s) red[tid] += red[tid + s];
        __syncthreads();
    }
    float inv = 1.f / red[0];
    __syncthreads();
    for (int i = tid; i < NPATCH; i += TPB) row[i] = sh[i] * inv;
}

// ------------------------- layernorm -----------------------------------------
__global__ void ln_kernel(const float* __restrict__ gamma, const float* __restrict__ beta) {
    int r = blockIdx.x;
    const float* x = g_comb + (long)r * DIM;
    __shared__ float red[TPB];
    __shared__ float red2[TPB];
    int tid = threadIdx.x;
    float s = 0.f, s2 = 0.f;
    for (int i = tid; i < DIM; i += TPB) {
        float v = x[i];
        s += v;
        s2 += v * v;
    }
    red[tid] = s; red2[tid] = s2;
    __syncthreads();
    for (int st = TPB / 2; st > 0; st >>= 1) {
        if (tid < st) { red[tid] += red[tid + st]; red2[tid] += red2[tid + st]; }
        __syncthreads();
    }
    float mu = red[0] / DIM;
    float var = red2[0] / DIM - mu * mu;
    float inv = rsqrtf(var + 1e-5f);
    for (int i = tid; i < DIM; i += TPB)
        g_ln[(long)r * DIM + i] = (x[i] - mu) * inv * gamma[i] + beta[i];
}

// ------------------------- launch --------------------------------------------
extern "C" void kernel_launch(void* const* d_in, const int* in_sizes, int n_in,
                              void* d_out, int out_size) {
    const float*         emb   = (const float*)d_in[0];
    const int*           ids   = (const int*)d_in[1];
    const unsigned char* msk   = (const unsigned char*)d_in[2];
    const float*         boxes = (const float*)d_in[3];
    const int*           thw   = (const int*)d_in[4];
    const int*           tok   = (const int*)d_in[5];
    const float*         Win   = (const float*)d_in[6];
    const float*         bin   = (const float*)d_in[7];
    const float*         Wout  = (const float*)d_in[8];
    const float*         bout  = (const float*)d_in[9];
    const float*         gam   = (const float*)d_in[10];
    const float*         bet   = (const float*)d_in[11];
    const float*         W1    = (const float*)d_in[12];
    const float*         b1    = (const float*)d_in[13];
    const float*         W2    = (const float*)d_in[14];
    const float*         b2    = (const float*)d_in[15];
    float*               out   = (float*)d_out;

    const float* Wq = Win;
    const float* Wk = Win + (long)DIM * DIM;
    const float* Wv = Win + 2L * DIM * DIM;
    const float* bv = bin + 2L * DIM;

    float *qtok, *q, *qk, *scores, *u, *ctx, *comb, *ln, *hidden, *rows, *part;
    int *start;
    cudaGetSymbolAddress((void**)&qtok,   g_qtok);
    cudaGetSymbolAddress((void**)&q,      g_q);
    cudaGetSymbolAddress((void**)&qk,     g_qk);
    cudaGetSymbolAddress((void**)&scores, g_scores);
    cudaGetSymbolAddress((void**)&u,      g_u);
    cudaGetSymbolAddress((void**)&ctx,    g_ctx);
    cudaGetSymbolAddress((void**)&comb,   g_comb);
    cudaGetSymbolAddress((void**)&ln,     g_ln);
    cudaGetSymbolAddress((void**)&hidden, g_hidden);
    cudaGetSymbolAddress((void**)&rows,   g_rows);
    cudaGetSymbolAddress((void**)&part,   g_part);
    cudaGetSymbolAddress((void**)&start,  g_start);

    const float scale = 1.0f / sqrtf((float)DHD);
    const long n4 = (long)BATCH * SEQ * DIM / 4;

    // 1. output base copy
    copy_kernel<<<8192, TPB>>>((const float4*)emb, (float4*)out, n4);
    // 2. positions + patch start
    scan_kernel<<<BATCH, TPB>>>(ids, msk, tok);
    // 3. gather query tokens
    gather_kernel<<<NTOK, TPB>>>(emb);

    // 4. q = (qtok @ Wq^T + bq) * scale   SK=16 (Kc=224), 112 blocks
    skinny_tb<<<dim3(7, 16, 1), TPB>>>(qtok, DIM, 0, Wq, DIM, 0, part, DIM, DIM, 16);
    combine_kernel<<<(NTOK * DIM + TPB - 1) / TPB, TPB>>>(
        part, 16, q, DIM, 0, NTOK, DIM, bin, 0, nullptr, 0, scale, 0, NTOK * DIM);

    // 5. qk[t,h,:] = q[t,h,:] @ Wk_h   (NN), SK=4 (Kc=112), 128 blocks
    skinny_nn<<<dim3(4, 4, NHD), TPB>>>(q, DIM, DHD, Wk, DIM, (long)DHD * DIM,
                                        part, DIM, DHD, 4);
    combine_kernel<<<(NHD * NTOK * DIM + TPB - 1) / TPB, TPB>>>(
        part, 4, qk, NHD * DIM, DIM, NTOK, DIM, nullptr, 0, nullptr, 0, 1.f, 0,
        NHD * NTOK * DIM);

    // 6. scores = qk @ patches^T   SK=7 (kLen=512), 896 blocks
    gemm_kernel<96, 64, 32, 6, 4, true, 7><<<dim3(NPATCH / 64, 7, BATCH), TPB>>>(
        qk, DIM, (long)NBOX * NHD * DIM,
        emb, DIM, (long)SEQ * DIM,
        part, 0, 0, NBOX * NHD, NPATCH, DIM, start);
    combine_kernel<<<(BATCH * 96 * NPATCH + TPB - 1) / TPB, TPB>>>(
        part, 7, scores, NPATCH, (long)NBOX * NHD * NPATCH, 96, NPATCH,
        nullptr, 0, nullptr, 0, 1.f, 0, BATCH * 96 * NPATCH);

    // 7. masked softmax
    softmax_kernel<<<BATCH * NBOX * NHD, TPB>>>(scores, boxes, thw);

    // 8. u = attn @ patches   SK=8 (kLen=512), 896 blocks
    gemm_kernel<96, 64, 32, 6, 4, false, 8><<<dim3(DIM / 64, 8, BATCH), TPB>>>(
        scores, NPATCH, (long)NBOX * NHD * NPATCH,
        emb, DIM, (long)SEQ * DIM,
        part, 0, 0, NBOX * NHD, DIM, NPATCH, start);
    combine_kernel<<<(BATCH * 96 * DIM + TPB - 1) / TPB, TPB>>>(
        part, 8, u, DIM, (long)96 * DIM, 96, DIM,
        nullptr, 0, nullptr, 0, 1.f, 0, BATCH * 96 * DIM);

    // 9. ctx[:, h] = u_h @ Wv_h^T + bv_h   SK=16 (Kc=224), 128 blocks
    skinny_tb<<<dim3(1, 16, NHD), TPB>>>(u, NHD * DIM, DIM, Wv, DIM, (long)DHD * DIM,
                                         part, DHD, DIM, 16);
    combine_kernel<<<(NHD * NTOK * DHD + TPB - 1) / TPB, TPB>>>(
        part, 16, ctx, DIM, DHD, NTOK, DHD, bv, DHD, nullptr, 0, 1.f, 0,
        NHD * NTOK * DHD);

    // 10. combined = ctx @ Wout^T + bout + qtok   SK=16
    skinny_tb<<<dim3(7, 16, 1), TPB>>>(ctx, DIM, 0, Wout, DIM, 0, part, DIM, DIM, 16);
    combine_kernel<<<(NTOK * DIM + TPB - 1) / TPB, TPB>>>(
        part, 16, comb, DIM, 0, NTOK, DIM, bout, 0, qtok, 0, 1.f, 0, NTOK * DIM);

    // 11. layernorm
    ln_kernel<<<NTOK, TPB>>>(gam, bet);

    // 12. hidden = gelu(ln @ W1^T + b1)   SK=8 (Kc=448), 112 blocks
    skinny_tb<<<dim3(14, 8, 1), TPB>>>(ln, DIM, 0, W1, DIM, 0, part, DFF, DIM, 8);
    combine_kernel<<<(NTOK * DFF + TPB - 1) / TPB, TPB>>>(
        part, 8, hidden, DFF, 0, NTOK, DFF, b1, 0, nullptr, 0, 1.f, 1, NTOK * DFF);

    // 13. rows = ln + hidden @ W2^T + b2   SK=16 (Kc=448), 112 blocks
    skinny_tb<<<dim3(7, 16, 1), TPB>>>(hidden, DFF, 0, W2, DFF, 0, part, DIM, DFF, 16);
    combine_kernel<<<(NTOK * DIM + TPB - 1) / TPB, TPB>>>(
        part, 16, rows, DIM, 0, NTOK, DIM, b2, 0, ln, 0, 1.f, 0, NTOK * DIM);

    // 14. scatter
    scatter_kernel<<<NTOK, TPB>>>(out);
}

// round 4
// speedup vs baseline: 1.4804x; 1.1356x over previous
#include <cuda_runtime.h>
#include <math.h>

#define BATCH   2
#define SEQ     4608
#define DIM     3584
#define NHD     8
#define DHD     448
#define NPATCH  4096
#define NBOX    12
#define DFF     7168
#define NTOK    24
#define TPB     256

// ------------------------- scratch ------------------------------------------
__device__ int   g_pos[NTOK];
__device__ int   g_start[BATCH];
__device__ float g_qtok[NTOK * DIM];
__device__ float g_q[NTOK * DIM];
__device__ float g_qk[NTOK * NHD * DIM];
__device__ float g_scores[BATCH * NBOX * NHD * NPATCH];
__device__ float g_u[NTOK * NHD * DIM];
__device__ float g_ctx[NTOK * DIM];
__device__ float g_comb[NTOK * DIM];
__device__ float g_ln[NTOK * DIM];
__device__ float g_hidden[NTOK * DFF];
__device__ float g_rows[NTOK * DIM];
__device__ float g_part[5505024];          // split-K partial scratch (22 MB)

// ------------------------- simple kernels ------------------------------------
__global__ void copy_kernel(const float4* __restrict__ src, float4* __restrict__ dst, long n4) {
    long i = (long)blockIdx.x * blockDim.x + threadIdx.x;
    long stride = (long)gridDim.x * blockDim.x;
    for (; i < n4; i += stride) dst[i] = src[i];
}

__global__ void scan_kernel(const int* __restrict__ ids,
                            const unsigned char* __restrict__ mask,
                            const int* __restrict__ tokPtr) {
    int b = blockIdx.x;
    __shared__ int sh[SEQ];
    __shared__ int s_f0, s_es, s_off, s_first;
    int tid = threadIdx.x;

    if (tid == 0) s_f0 = 0x7fffffff;
    __syncthreads();
    for (int i = tid; i < SEQ; i += blockDim.x) {
        if (mask[i] != 0) { atomicMin(&s_f0, i); break; }
    }
    __syncthreads();
    if (tid == 0) {
        int f0 = s_f0;
        unsigned char b0 = mask[f0];
        unsigned char b1 = mask[f0 + 1];
        if (b0 == 1u && b1 == 0u)      { s_es = 4; s_off = 0; }
        else if (b0 == 0x80u)          { s_es = 4; s_off = 2; }
        else                           { s_es = 1; s_off = 0; }
        s_first = SEQ;
    }
    __syncthreads();
    int es = s_es, off = s_off;
    for (int i = tid; i < SEQ; i += blockDim.x)
        if (mask[((long)b * SEQ + i) * es + off] != 0) atomicMin(&s_first, i);
    __syncthreads();
    if (tid == 0) g_start[b] = s_first;

    for (int i = tid; i < SEQ; i += blockDim.x)
        sh[i] = ids[(long)b * SEQ + i];
    __syncthreads();
    if (tid < 32) {
        int tok = *tokPtr;
        int count = 0;
        for (int base = 0; base < SEQ && count < NBOX; base += 32) {
            unsigned bal = __ballot_sync(0xffffffffu, sh[base + tid] == tok);
            while (bal && count < NBOX) {
                int o = __ffs(bal) - 1;
                if (tid == 0) g_pos[b * NBOX + count] = base + o;
                count++;
                bal &= bal - 1;
            }
        }
    }
}

__global__ void gather_kernel(const float* __restrict__ emb) {
    int r = blockIdx.x;
    int b = r / NBOX;
    const float* src = emb + ((long)b * SEQ + g_pos[r]) * DIM;
    for (int i = threadIdx.x; i < DIM; i += blockDim.x) g_qtok[(long)r * DIM + i] = src[i];
}

__global__ void scatter_kernel(float* __restrict__ out) {
    int r = blockIdx.x;
    int b = r / NBOX;
    float* dst = out + ((long)b * SEQ + g_pos[r]) * DIM;
    for (int i = threadIdx.x; i < DIM; i += blockDim.x) dst[i] = g_rows[(long)r * DIM + i];
}

// ------------------------- streamed skinny GEMM (TB) -------------------------
// C[24,N] = A[24,K] @ W[N,K]^T. One column per thread, Kc<=128 per block,
// A chunk in smem (broadcast LDS.128), W streamed with reg double-buffer.
__global__ __launch_bounds__(TPB) void skinny_tb(
    const float* __restrict__ A, int lda, long Az,
    const float* __restrict__ W, int ldw, long Wz,
    float* __restrict__ P, int N, int K, int SK)
{
    const int z = blockIdx.z, s = blockIdx.y;
    const int n0 = blockIdx.x * TPB;
    const int Kc = K / SK;            // <= 128
    const int kBeg = s * Kc;
    A += (long)z * Az;
    W += (long)z * Wz;

    __shared__ float a_sm[NTOK * 128];
    const int tid = threadIdx.x;
    for (int i = tid; i < NTOK * (Kc / 4); i += TPB) {
        int m = i / (Kc / 4), kc = i % (Kc / 4);
        *reinterpret_cast<float4*>(&a_sm[m * Kc + kc * 4]) =
            *reinterpret_cast<const float4*>(A + (long)m * lda + kBeg + kc * 4);
    }
    __syncthreads();

    const int n = n0 + tid;
    const bool valid = n < N;
    const float* wp = W + (long)(valid ? n : 0) * ldw + kBeg;

    float acc[NTOK];
#pragma unroll
    for (int m = 0; m < NTOK; m++) acc[m] = 0.f;

    float4 wc = *reinterpret_cast<const float4*>(wp);
    for (int k = 0; k < Kc; k += 4) {
        float4 wn;
        if (k + 4 < Kc) wn = *reinterpret_cast<const float4*>(wp + k + 4);
#pragma unroll
        for (int m = 0; m < NTOK; m++) {
            float4 a = *reinterpret_cast<const float4*>(&a_sm[m * Kc + k]);
            acc[m] = fmaf(a.x, wc.x, acc[m]);
            acc[m] = fmaf(a.y, wc.y, acc[m]);
            acc[m] = fmaf(a.z, wc.z, acc[m]);
            acc[m] = fmaf(a.w, wc.w, acc[m]);
        }
        wc = wn;
    }
    if (valid) {
        long base = ((long)(z * SK + s) * NTOK) * N;
#pragma unroll
        for (int m = 0; m < NTOK; m++) P[base + (long)m * N + n] = acc[m];
    }
}

// ------------------------- streamed skinny GEMM (NN) -------------------------
// C[24,N] = A[24,K] @ B[K,N]; B contiguous along n (coalesced float4).
__global__ __launch_bounds__(TPB) void skinny_nn(
    const float* __restrict__ A, int lda, long Az,
    const float* __restrict__ W, int ldw, long Wz,
    float* __restrict__ P, int N, int K, int SK)
{
    const int z = blockIdx.z, s = blockIdx.y;
    const int n0 = blockIdx.x * (TPB * 4);
    const int Kc = K / SK;            // <= 112
    const int kBeg = s * Kc;
    A += (long)z * Az;
    W += (long)z * Wz;

    __shared__ float a_sm[NTOK * 112];
    const int tid = threadIdx.x;
    for (int i = tid; i < NTOK * Kc; i += TPB) {
        int m = i / Kc, k = i % Kc;
        a_sm[m * Kc + k] = A[(long)m * lda + kBeg + k];
    }
    __syncthreads();

    const int n = n0 + tid * 4;
    if (n >= N) return;
    float4 acc[NTOK];
#pragma unroll
    for (int m = 0; m < NTOK; m++) acc[m] = make_float4(0, 0, 0, 0);

    const float* wp = W + (long)kBeg * ldw + n;
    float4 wc = *reinterpret_cast<const float4*>(wp);
    for (int k = 0; k < Kc; k++) {
        float4 wn;
        if (k + 1 < Kc) wn = *reinterpret_cast<const float4*>(wp + (long)(k + 1) * ldw);
#pragma unroll
        for (int m = 0; m < NTOK; m++) {
            float a = a_sm[m * Kc + k];
            acc[m].x = fmaf(a, wc.x, acc[m].x);
            acc[m].y = fmaf(a, wc.y, acc[m].y);
            acc[m].z = fmaf(a, wc.z, acc[m].z);
            acc[m].w = fmaf(a, wc.w, acc[m].w);
        }
        wc = wn;
    }
    long base = ((long)(z * SK + s) * NTOK) * N;
#pragma unroll
    for (int m = 0; m < NTOK; m++)
        *reinterpret_cast<float4*>(&P[base + (long)m * N + n]) = acc[m];
}

// ------------------------- big GEMM (register tiled, split-K partials) -------
template<int BM, int BN, int BK, int TM, int TN, bool TB, int SK>
__global__ __launch_bounds__(TPB) void gemm_kernel(
    const float* __restrict__ A, int lda, long Az,
    const float* __restrict__ B, int ldb, long Bz,
    float* __restrict__ C, int ldc, long Cz,
    int M, int N, int K,
    const int* __restrict__ patchStart)
{
    const int z  = blockIdx.z;
    const int n0 = blockIdx.x * BN;
    const int s  = blockIdx.y;
    const int kLen = K / SK;
    const int kBeg = s * kLen;

    A += (long)z * Az;
    B += (long)z * Bz;
    if (patchStart) B += (long)patchStart[z] * ldb;

    __shared__ float a_sm[BK][BM];
    __shared__ float b_sm[BK][BN];

    float acc[TM][TN];
#pragma unroll
    for (int i = 0; i < TM; i++)
#pragma unroll
        for (int j = 0; j < TN; j++) acc[i][j] = 0.f;

    const int tid = threadIdx.x;
    constexpr int NTX = BN / TN;
    const int tx = tid % NTX;
    const int ty = tid / NTX;

    for (int k0 = kBeg; k0 < kBeg + kLen; k0 += BK) {
#pragma unroll
        for (int i = tid; i < BM * BK / 4; i += TPB) {
            int mm = i / (BK / 4);
            int kc = i % (BK / 4);
            float4 v = *reinterpret_cast<const float4*>(A + (long)mm * lda + k0 + kc * 4);
            a_sm[kc * 4 + 0][mm] = v.x;
            a_sm[kc * 4 + 1][mm] = v.y;
            a_sm[kc * 4 + 2][mm] = v.z;
            a_sm[kc * 4 + 3][mm] = v.w;
        }
        if (TB) {
#pragma unroll
            for (int i = tid; i < BN * BK / 4; i += TPB) {
                int nn = i / (BK / 4);
                int kc = i % (BK / 4);
                float4 v = *reinterpret_cast<const float4*>(B + (long)(n0 + nn) * ldb + k0 + kc * 4);
                b_sm[kc * 4 + 0][nn] = v.x;
                b_sm[kc * 4 + 1][nn] = v.y;
                b_sm[kc * 4 + 2][nn] = v.z;
                b_sm[kc * 4 + 3][nn] = v.w;
            }
        } else {
#pragma unroll
            for (int i = tid; i < BK * BN / 4; i += TPB) {
                int kk = i / (BN / 4);
                int nc = i % (BN / 4);
                float4 v = *reinterpret_cast<const float4*>(B + (long)(k0 + kk) * ldb + n0 + nc * 4);
                *reinterpret_cast<float4*>(&b_sm[kk][nc * 4]) = v;
            }
        }
        __syncthreads();
#pragma unroll
        for (int kk = 0; kk < BK; kk++) {
            float af[TM], bf[TN];
#pragma unroll
            for (int i = 0; i < TM; i++) af[i] = a_sm[kk][ty * TM + i];
#pragma unroll
            for (int j = 0; j < TN; j++) bf[j] = b_sm[kk][tx * TN + j];
#pragma unroll
            for (int i = 0; i < TM; i++)
#pragma unroll
                for (int j = 0; j < TN; j++) acc[i][j] = fmaf(af[i], bf[j], acc[i][j]);
        }
        __syncthreads();
    }

#pragma unroll
    for (int i = 0; i < TM; i++) {
        int m = ty * TM + i;
#pragma unroll
        for (int j = 0; j < TN; j++) {
            int n = n0 + tx * TN + j;
            C[((long)(z * SK + s) * M + m) * N + n] = acc[i][j];
        }
    }
}

// reduce split-K partials + epilogue
__global__ void combine_kernel(const float* __restrict__ P, int SK,
                               float* __restrict__ C, int ldc, long Cz, int M, int N,
                               const float* __restrict__ bias, long biasZ,
                               const float* __restrict__ resid, long residZ,
                               float scale, int act, int total) {
    int idx = blockIdx.x * blockDim.x + threadIdx.x;
    if (idx >= total) return;
    int n = idx % N;
    int t = idx / N;
    int m = t % M;
    int z = t / M;
    float v = 0.f;
    for (int s = 0; s < SK; s++) v += P[((long)(z * SK + s) * M + m) * N + n];
    if (bias)  v += bias[z * biasZ + n];
    v *= scale;
    if (act)   v = v * normcdff(v);
    if (resid) v += resid[z * residZ + (long)m * ldc + n];
    C[z * Cz + (long)m * ldc + n] = v;
}

// ------------------------- masked softmax ------------------------------------
__global__ void softmax_kernel(float* __restrict__ scores,
                               const float* __restrict__ boxes,
                               const int* __restrict__ thw) {
    int blk = blockIdx.x;
    int b = blk / (NBOX * NHD);
    int n = (blk / NHD) % NBOX;
    int hg = thw[1], wg = thw[2];
    const float* bx = boxes + (long)(b * NBOX + n) * 4;
    float x1 = bx[0], y1 = bx[1], x2 = bx[2], y2 = bx[3];
    int px1 = min(max((int)floorf(x1 * (float)wg), 0), wg - 1);
    int px2 = max(px1 + 1, min((int)floorf(x2 * (float)wg), wg));
    int py1 = min(max((int)floorf(y1 * (float)hg), 0), hg - 1);
    int py2 = max(py1 + 1, min((int)floorf(y2 * (float)hg), hg));

    float* row = scores + (long)blk * NPATCH;
    __shared__ float sh[NPATCH];
    __shared__ float red[TPB];
    int tid = threadIdx.x;
    int hw = hg * wg;

    float mx = -1e30f;
    for (int i = tid; i < NPATCH; i += TPB) {
        int q = i % hw;
        int rr = q / wg, cc = q % wg;
        bool in = (rr >= py1) && (rr < py2) && (cc >= px1) && (cc < px2);
        float v = in ? row[i] : -1e30f;
        sh[i] = v;
        mx = fmaxf(mx, v);
    }
    red[tid] = mx;
    __syncthreads();
    for (int s = TPB / 2; s > 0; s >>= 1) {
        if (tid < s) red[tid] = fmaxf(red[tid], red[tid + s]);
        __syncthreads();
    }
    float maxv = red[0];
    __syncthreads();

    float sum = 0.f;
    for (int i = tid; i < NPATCH; i += TPB) {
        float e = expf(sh[i] - maxv);
        sh[i] = e;
        sum += e;
    }
    red[tid] = sum;
    __syncthreads();
    for (int s = TPB / 2; s > 0; s >>= 1) {
        if (tid < s) red[tid] += red[tid + s];
        __syncthreads();
    }
    float inv = 1.f / red[0];
    __syncthreads();
    for (int i = tid; i < NPATCH; i += TPB) row[i] = sh[i] * inv;
}

// ------------------------- layernorm -----------------------------------------
__global__ void ln_kernel(const float* __restrict__ gamma, const float* __restrict__ beta) {
    int r = blockIdx.x;
    const float* x = g_comb + (long)r * DIM;
    __shared__ float red[TPB];
    __shared__ float red2[TPB];
    int tid = threadIdx.x;
    float s = 0.f, s2 = 0.f;
    for (int i = tid; i < DIM; i += TPB) {
        float v = x[i];
        s += v;
        s2 += v * v;
    }
    red[tid] = s; red2[tid] = s2;
    __syncthreads();
    for (int st = TPB / 2; st > 0; st >>= 1) {
        if (tid < st) { red[tid] += red[tid + st]; red2[tid] += red2[tid + st]; }
        __syncthreads();
    }
    float mu = red[0] / DIM;
    float var = red2[0] / DIM - mu * mu;
    float inv = rsqrtf(var + 1e-5f);
    for (int i = tid; i < DIM; i += TPB)
        g_ln[(long)r * DIM + i] = (x[i] - mu) * inv * gamma[i] + beta[i];
}

// ------------------------- launch --------------------------------------------
extern "C" void kernel_launch(void* const* d_in, const int* in_sizes, int n_in,
                              void* d_out, int out_size) {
    const float*         emb   = (const float*)d_in[0];
    const int*           ids   = (const int*)d_in[1];
    const unsigned char* msk   = (const unsigned char*)d_in[2];
    const float*         boxes = (const float*)d_in[3];
    const int*           thw   = (const int*)d_in[4];
    const int*           tok   = (const int*)d_in[5];
    const float*         Win   = (const float*)d_in[6];
    const float*         bin   = (const float*)d_in[7];
    const float*         Wout  = (const float*)d_in[8];
    const float*         bout  = (const float*)d_in[9];
    const float*         gam   = (const float*)d_in[10];
    const float*         bet   = (const float*)d_in[11];
    const float*         W1    = (const float*)d_in[12];
    const float*         b1    = (const float*)d_in[13];
    const float*         W2    = (const float*)d_in[14];
    const float*         b2    = (const float*)d_in[15];
    float*               out   = (float*)d_out;

    const float* Wq = Win;
    const float* Wk = Win + (long)DIM * DIM;
    const float* Wv = Win + 2L * DIM * DIM;
    const float* bv = bin + 2L * DIM;

    float *qtok, *q, *qk, *scores, *u, *ctx, *comb, *ln, *hidden, *rows, *part;
    int *start;
    cudaGetSymbolAddress((void**)&qtok,   g_qtok);
    cudaGetSymbolAddress((void**)&q,      g_q);
    cudaGetSymbolAddress((void**)&qk,     g_qk);
    cudaGetSymbolAddress((void**)&scores, g_scores);
    cudaGetSymbolAddress((void**)&u,      g_u);
    cudaGetSymbolAddress((void**)&ctx,    g_ctx);
    cudaGetSymbolAddress((void**)&comb,   g_comb);
    cudaGetSymbolAddress((void**)&ln,     g_ln);
    cudaGetSymbolAddress((void**)&hidden, g_hidden);
    cudaGetSymbolAddress((void**)&rows,   g_rows);
    cudaGetSymbolAddress((void**)&part,   g_part);
    cudaGetSymbolAddress((void**)&start,  g_start);

    const float scale = 1.0f / sqrtf((float)DHD);
    const long n4 = (long)BATCH * SEQ * DIM / 4;

    // 1. output base copy
    copy_kernel<<<8192, TPB>>>((const float4*)emb, (float4*)out, n4);
    // 2. positions + patch start
    scan_kernel<<<BATCH, TPB>>>(ids, msk, tok);
    // 3. gather query tokens
    gather_kernel<<<NTOK, TPB>>>(emb);

    // 4. q = (qtok @ Wq^T + bq) * scale   SK=28 (Kc=128), 392 blocks
    skinny_tb<<<dim3(14, 28, 1), TPB>>>(qtok, DIM, 0, Wq, DIM, 0, part, DIM, DIM, 28);
    combine_kernel<<<(NTOK * DIM + TPB - 1) / TPB, TPB>>>(
        part, 28, q, DIM, 0, NTOK, DIM, bin, 0, nullptr, 0, scale, 0, NTOK * DIM);

    // 5. qk[t,h,:] = q[t,h,:] @ Wk_h   (NN), SK=8 (Kc=56), 256 blocks
    skinny_nn<<<dim3(4, 8, NHD), TPB>>>(q, DIM, DHD, Wk, DIM, (long)DHD * DIM,
                                        part, DIM, DHD, 8);
    combine_kernel<<<(NHD * NTOK * DIM + TPB - 1) / TPB, TPB>>>(
        part, 8, qk, NHD * DIM, DIM, NTOK, DIM, nullptr, 0, nullptr, 0, 1.f, 0,
        NHD * NTOK * DIM);

    // 6. scores = qk @ patches^T   SK=7 (kLen=512), 896 blocks
    gemm_kernel<96, 64, 32, 6, 4, true, 7><<<dim3(NPATCH / 64, 7, BATCH), TPB>>>(
        qk, DIM, (long)NBOX * NHD * DIM,
        emb, DIM, (long)SEQ * DIM,
        part, 0, 0, NBOX * NHD, NPATCH, DIM, start);
    combine_kernel<<<(BATCH * 96 * NPATCH + TPB - 1) / TPB, TPB>>>(
        part, 7, scores, NPATCH, (long)NBOX * NHD * NPATCH, 96, NPATCH,
        nullptr, 0, nullptr, 0, 1.f, 0, BATCH * 96 * NPATCH);

    // 7. masked softmax
    softmax_kernel<<<BATCH * NBOX * NHD, TPB>>>(scores, boxes, thw);

    // 8. u = attn @ patches   SK=8 (kLen=512), 896 blocks
    gemm_kernel<96, 64, 32, 6, 4, false, 8><<<dim3(DIM / 64, 8, BATCH), TPB>>>(
        scores, NPATCH, (long)NBOX * NHD * NPATCH,
        emb, DIM, (long)SEQ * DIM,
        part, 0, 0, NBOX * NHD, DIM, NPATCH, start);
    combine_kernel<<<(BATCH * 96 * DIM + TPB - 1) / TPB, TPB>>>(
        part, 8, u, DIM, (long)96 * DIM, 96, DIM,
        nullptr, 0, nullptr, 0, 1.f, 0, BATCH * 96 * DIM);

    // 9. ctx[:, h] = u_h @ Wv_h^T + bv_h   SK=28, 448 blocks
    skinny_tb<<<dim3(2, 28, NHD), TPB>>>(u, NHD * DIM, DIM, Wv, DIM, (long)DHD * DIM,
                                         part, DHD, DIM, 28);
    combine_kernel<<<(NHD * NTOK * DHD + TPB - 1) / TPB, TPB>>>(
        part, 28, ctx, DIM, DHD, NTOK, DHD, bv, DHD, nullptr, 0, 1.f, 0,
        NHD * NTOK * DHD);

    // 10. combined = ctx @ Wout^T + bout + qtok   SK=28, 392 blocks
    skinny_tb<<<dim3(14, 28, 1), TPB>>>(ctx, DIM, 0, Wout, DIM, 0, part, DIM, DIM, 28);
    combine_kernel<<<(NTOK * DIM + TPB - 1) / TPB, TPB>>>(
        part, 28, comb, DIM, 0, NTOK, DIM, bout, 0, qtok, 0, 1.f, 0, NTOK * DIM);

    // 11. layernorm
    ln_kernel<<<NTOK, TPB>>>(gam, bet);

    // 12. hidden = gelu(ln @ W1^T + b1)   SK=28, 784 blocks
    skinny_tb<<<dim3(28, 28, 1), TPB>>>(ln, DIM, 0, W1, DIM, 0, part, DFF, DIM, 28);
    combine_kernel<<<(NTOK * DFF + TPB - 1) / TPB, TPB>>>(
        part, 28, hidden, DFF, 0, NTOK, DFF, b1, 0, nullptr, 0, 1.f, 1, NTOK * DFF);

    // 13. rows = ln + hidden @ W2^T + b2   SK=56 (Kc=128), 784 blocks
    skinny_tb<<<dim3(14, 56, 1), TPB>>>(hidden, DFF, 0, W2, DFF, 0, part, DIM, DFF, 56);
    combine_kernel<<<(NTOK * DIM + TPB - 1) / TPB, TPB>>>(
        part, 56, rows, DIM, 0, NTOK, DIM, b2, 0, ln, 0, 1.f, 0, NTOK * DIM);

    // 14. scatter
    scatter_kernel<<<NTOK, TPB>>>(out);
}

// round 5
// speedup vs baseline: 2.0966x; 1.4162x over previous
#include <cuda_runtime.h>
#include <math.h>

#define BATCH   2
#define SEQ     4608
#define DIM     3584
#define NHD     8
#define DHD     448
#define NPATCH  4096
#define NBOX    12
#define DFF     7168
#define NTOK    24
#define TPB     256

// ------------------------- scratch ------------------------------------------
__device__ int   g_pos[NTOK];
__device__ int   g_start[BATCH];
__device__ float g_qtok[NTOK * DIM];
__device__ float g_q[NTOK * DIM];
__device__ float g_qk[NTOK * NHD * DIM];
__device__ float g_scores[BATCH * NBOX * NHD * NPATCH];
__device__ float g_u[NTOK * NHD * DIM];
__device__ float g_ctx[NTOK * DIM];
__device__ float g_comb[NTOK * DIM];
__device__ float g_ln[NTOK * DIM];
__device__ float g_hidden[NTOK * DFF];
__device__ float g_rows[NTOK * DIM];
__device__ float g_part[5505024];          // split-K partial scratch (22 MB)

// ------------------------- simple kernels ------------------------------------
__global__ void copy_kernel(const float4* __restrict__ src, float4* __restrict__ dst, long n4) {
    long i = (long)blockIdx.x * blockDim.x + threadIdx.x;
    long stride = (long)gridDim.x * blockDim.x;
    for (; i < n4; i += stride) dst[i] = src[i];
}

__global__ void scan_kernel(const int* __restrict__ ids,
                            const unsigned char* __restrict__ mask,
                            const int* __restrict__ tokPtr) {
    int b = blockIdx.x;
    __shared__ int sh[SEQ];
    __shared__ int s_f0, s_es, s_off, s_first;
    int tid = threadIdx.x;

    if (tid == 0) s_f0 = 0x7fffffff;
    __syncthreads();
    for (int i = tid; i < SEQ; i += blockDim.x) {
        if (mask[i] != 0) { atomicMin(&s_f0, i); break; }
    }
    __syncthreads();
    if (tid == 0) {
        int f0 = s_f0;
        unsigned char b0 = mask[f0];
        unsigned char b1 = mask[f0 + 1];
        if (b0 == 1u && b1 == 0u)      { s_es = 4; s_off = 0; }
        else if (b0 == 0x80u)          { s_es = 4; s_off = 2; }
        else                           { s_es = 1; s_off = 0; }
        s_first = SEQ;
    }
    __syncthreads();
    int es = s_es, off = s_off;
    for (int i = tid; i < SEQ; i += blockDim.x)
        if (mask[((long)b * SEQ + i) * es + off] != 0) atomicMin(&s_first, i);
    __syncthreads();
    if (tid == 0) g_start[b] = s_first;

    for (int i = tid; i < SEQ; i += blockDim.x)
        sh[i] = ids[(long)b * SEQ + i];
    __syncthreads();
    if (tid < 32) {
        int tok = *tokPtr;
        int count = 0;
        for (int base = 0; base < SEQ && count < NBOX; base += 32) {
            unsigned bal = __ballot_sync(0xffffffffu, sh[base + tid] == tok);
            while (bal && count < NBOX) {
                int o = __ffs(bal) - 1;
                if (tid == 0) g_pos[b * NBOX + count] = base + o;
                count++;
                bal &= bal - 1;
            }
        }
    }
}

__global__ void gather_kernel(const float* __restrict__ emb) {
    int r = blockIdx.x;
    int b = r / NBOX;
    const float* src = emb + ((long)b * SEQ + g_pos[r]) * DIM;
    for (int i = threadIdx.x; i < DIM; i += blockDim.x) g_qtok[(long)r * DIM + i] = src[i];
}

__global__ void scatter_kernel(float* __restrict__ out) {
    int r = blockIdx.x;
    int b = r / NBOX;
    float* dst = out + ((long)b * SEQ + g_pos[r]) * DIM;
    for (int i = threadIdx.x; i < DIM; i += blockDim.x) dst[i] = g_rows[(long)r * DIM + i];
}

// ------------------------- streamed skinny GEMM (TB) -------------------------
__global__ __launch_bounds__(TPB) void skinny_tb(
    const float* __restrict__ A, int lda, long Az,
    const float* __restrict__ W, int ldw, long Wz,
    float* __restrict__ P, int N, int K, int SK)
{
    const int z = blockIdx.z, s = blockIdx.y;
    const int n0 = blockIdx.x * TPB;
    const int Kc = K / SK;
    const int kBeg = s * Kc;
    A += (long)z * Az;
    W += (long)z * Wz;

    __shared__ float a_sm[NTOK * 128];
    const int tid = threadIdx.x;
    for (int i = tid; i < NTOK * (Kc / 4); i += TPB) {
        int m = i / (Kc / 4), kc = i % (Kc / 4);
        *reinterpret_cast<float4*>(&a_sm[m * Kc + kc * 4]) =
            *reinterpret_cast<const float4*>(A + (long)m * lda + kBeg + kc * 4);
    }
    __syncthreads();

    const int n = n0 + tid;
    const bool valid = n < N;
    const float* wp = W + (long)(valid ? n : 0) * ldw + kBeg;

    float acc[NTOK];
#pragma unroll
    for (int m = 0; m < NTOK; m++) acc[m] = 0.f;

    float4 wc = *reinterpret_cast<const float4*>(wp);
    for (int k = 0; k < Kc; k += 4) {
        float4 wn;
        if (k + 4 < Kc) wn = *reinterpret_cast<const float4*>(wp + k + 4);
#pragma unroll
        for (int m = 0; m < NTOK; m++) {
            float4 a = *reinterpret_cast<const float4*>(&a_sm[m * Kc + k]);
            acc[m] = fmaf(a.x, wc.x, acc[m]);
            acc[m] = fmaf(a.y, wc.y, acc[m]);
            acc[m] = fmaf(a.z, wc.z, acc[m]);
            acc[m] = fmaf(a.w, wc.w, acc[m]);
        }
        wc = wn;
    }
    if (valid) {
        long base = ((long)(z * SK + s) * NTOK) * N;
#pragma unroll
        for (int m = 0; m < NTOK; m++) P[base + (long)m * N + n] = acc[m];
    }
}

// ------------------------- streamed skinny GEMM (NN) -------------------------
__global__ __launch_bounds__(TPB) void skinny_nn(
    const float* __restrict__ A, int lda, long Az,
    const float* __restrict__ W, int ldw, long Wz,
    float* __restrict__ P, int N, int K, int SK)
{
    const int z = blockIdx.z, s = blockIdx.y;
    const int n0 = blockIdx.x * (TPB * 4);
    const int Kc = K / SK;
    const int kBeg = s * Kc;
    A += (long)z * Az;
    W += (long)z * Wz;

    __shared__ float a_sm[NTOK * 112];
    const int tid = threadIdx.x;
    for (int i = tid; i < NTOK * Kc; i += TPB) {
        int m = i / Kc, k = i % Kc;
        a_sm[m * Kc + k] = A[(long)m * lda + kBeg + k];
    }
    __syncthreads();

    const int n = n0 + tid * 4;
    if (n >= N) return;
    float4 acc[NTOK];
#pragma unroll
    for (int m = 0; m < NTOK; m++) acc[m] = make_float4(0, 0, 0, 0);

    const float* wp = W + (long)kBeg * ldw + n;
    float4 wc = *reinterpret_cast<const float4*>(wp);
    for (int k = 0; k < Kc; k++) {
        float4 wn;
        if (k + 1 < Kc) wn = *reinterpret_cast<const float4*>(wp + (long)(k + 1) * ldw);
#pragma unroll
        for (int m = 0; m < NTOK; m++) {
            float a = a_sm[m * Kc + k];
            acc[m].x = fmaf(a, wc.x, acc[m].x);
            acc[m].y = fmaf(a, wc.y, acc[m].y);
            acc[m].z = fmaf(a, wc.z, acc[m].z);
            acc[m].w = fmaf(a, wc.w, acc[m].w);
        }
        wc = wn;
    }
    long base = ((long)(z * SK + s) * NTOK) * N;
#pragma unroll
    for (int m = 0; m < NTOK; m++)
        *reinterpret_cast<float4*>(&P[base + (long)m * N + n]) = acc[m];
}

// ------------------------- tf32 tensor-core GEMM -----------------------------
// C[96,N] = A[96,K] @ (TB ? B[n,k]^T : B[k,n]),  per z, split-K partials.
// BM=96, BN=64, BK=32. 8 warps, each m48 x n16. mma.sync.m16n8k8 tf32.
// A,B fed as raw fp32 bits (tf32 truncation, eps ~2^-12).
template<bool TB>
__global__ __launch_bounds__(TPB) void mma_gemm(
    const float* __restrict__ A, long Az,
    const float* __restrict__ B, long Bz,
    float* __restrict__ P, int N, int K, int SK,
    const int* __restrict__ patchStart)
{
    const int z = blockIdx.z, s = blockIdx.y;
    const int n0 = blockIdx.x * 64;
    const int kLen = K / SK;
    const int kBeg = s * kLen;
    A += (long)z * Az;
    B += (long)z * Bz + (long)patchStart[z] * DIM;

    __shared__ float Asm[96 * 36];      // [m][k], pad 36
    __shared__ float Bs[2304];          // TB: [n][36]; NN: [k][72]

    const int tid  = threadIdx.x;
    const int wid  = tid >> 5;
    const int lane = tid & 31;
    const int grp  = lane >> 2;         // 0..7
    const int th   = lane & 3;          // 0..3
    const int warpM = wid >> 2;         // 0..1 -> m offset *48
    const int warpN = wid & 3;          // 0..3 -> n offset *16

    float c[3][2][4];
#pragma unroll
    for (int i = 0; i < 3; i++)
#pragma unroll
        for (int j = 0; j < 2; j++)
#pragma unroll
            for (int r = 0; r < 4; r++) c[i][j][r] = 0.f;

    const int nTiles = kLen / 32;
    for (int t = 0; t < nTiles; t++) {
        const int k0 = kBeg + t * 32;
        // load A tile 96x32 (768 float4)
#pragma unroll
        for (int it = 0; it < 3; it++) {
            int idx = tid + it * TPB;
            int m = idx >> 3, kc = idx & 7;
            float4 v = *reinterpret_cast<const float4*>(A + (long)m * K + k0 + kc * 4);
            float* d = &Asm[m * 36 + kc * 4];
            d[0] = v.x; d[1] = v.y; d[2] = v.z; d[3] = v.w;
        }
        // load B tile (512 float4)
        if (TB) {
#pragma unroll
            for (int it = 0; it < 2; it++) {
                int idx = tid + it * TPB;
                int nn = idx >> 3, kc = idx & 7;
                float4 v = *reinterpret_cast<const float4*>(B + (long)(n0 + nn) * DIM + k0 + kc * 4);
                float* d = &Bs[nn * 36 + kc * 4];
                d[0] = v.x; d[1] = v.y; d[2] = v.z; d[3] = v.w;
            }
        } else {
#pragma unroll
            for (int it = 0; it < 2; it++) {
                int idx = tid + it * TPB;
                int kk = idx >> 4, nc = idx & 15;
                float4 v = *reinterpret_cast<const float4*>(B + (long)(k0 + kk) * DIM + n0 + nc * 4);
                float* d = &Bs[kk * 72 + nc * 4];
                d[0] = v.x; d[1] = v.y; d[2] = v.z; d[3] = v.w;
            }
        }
        __syncthreads();

#pragma unroll
        for (int q = 0; q < 32; q += 8) {
            unsigned a[3][4], b[2][2];
#pragma unroll
            for (int fr = 0; fr < 3; fr++) {
                int row = warpM * 48 + fr * 16 + grp;
                const unsigned* ap = reinterpret_cast<const unsigned*>(&Asm[row * 36 + q + th]);
                a[fr][0] = ap[0];
                a[fr][2] = ap[4];
                const unsigned* ap8 = reinterpret_cast<const unsigned*>(&Asm[(row + 8) * 36 + q + th]);
                a[fr][1] = ap8[0];
                a[fr][3] = ap8[4];
            }
#pragma unroll
            for (int fn = 0; fn < 2; fn++) {
                if (TB) {
                    int col = warpN * 16 + fn * 8 + grp;
                    const unsigned* bp = reinterpret_cast<const unsigned*>(&Bs[col * 36 + q + th]);
                    b[fn][0] = bp[0];
                    b[fn][1] = bp[4];
                } else {
                    int col = warpN * 16 + fn * 8 + grp;
                    b[fn][0] = reinterpret_cast<const unsigned*>(&Bs[(q + th) * 72 + col])[0];
                    b[fn][1] = reinterpret_cast<const unsigned*>(&Bs[(q + th + 4) * 72 + col])[0];
                }
            }
#pragma unroll
            for (int fr = 0; fr < 3; fr++)
#pragma unroll
                for (int fn = 0; fn < 2; fn++) {
                    asm volatile(
                        "mma.sync.aligned.m16n8k8.row.col.f32.tf32.tf32.f32 "
                        "{%0,%1,%2,%3}, {%4,%5,%6,%7}, {%8,%9}, {%0,%1,%2,%3};"
                        : "+f"(c[fr][fn][0]), "+f"(c[fr][fn][1]),
                          "+f"(c[fr][fn][2]), "+f"(c[fr][fn][3])
                        : "r"(a[fr][0]), "r"(a[fr][1]), "r"(a[fr][2]), "r"(a[fr][3]),
                          "r"(b[fn][0]), "r"(b[fn][1]));
                }
        }
        __syncthreads();
    }

    long base = (long)(z * SK + s) * 96 * N;
#pragma unroll
    for (int fr = 0; fr < 3; fr++) {
        int r0 = warpM * 48 + fr * 16 + grp;
#pragma unroll
        for (int fn = 0; fn < 2; fn++) {
            int col = n0 + warpN * 16 + fn * 8 + th * 2;
            *reinterpret_cast<float2*>(&P[base + (long)r0 * N + col]) =
                make_float2(c[fr][fn][0], c[fr][fn][1]);
            *reinterpret_cast<float2*>(&P[base + (long)(r0 + 8) * N + col]) =
                make_float2(c[fr][fn][2], c[fr][fn][3]);
        }
    }
}

// reduce split-K partials + epilogue
__global__ void combine_kernel(const float* __restrict__ P, int SK,
                               float* __restrict__ C, int ldc, long Cz, int M, int N,
                               const float* __restrict__ bias, long biasZ,
                               const float* __restrict__ resid, long residZ,
                               float scale, int act, int total) {
    int idx = blockIdx.x * blockDim.x + threadIdx.x;
    if (idx >= total) return;
    int n = idx % N;
    int t = idx / N;
    int m = t % M;
    int z = t / M;
    float v = 0.f;
    for (int s = 0; s < SK; s++) v += P[((long)(z * SK + s) * M + m) * N + n];
    if (bias)  v += bias[z * biasZ + n];
    v *= scale;
    if (act)   v = v * normcdff(v);
    if (resid) v += resid[z * residZ + (long)m * ldc + n];
    C[z * Cz + (long)m * ldc + n] = v;
}

// ------------------------- masked softmax ------------------------------------
__global__ void softmax_kernel(float* __restrict__ scores,
                               const float* __restrict__ boxes,
                               const int* __restrict__ thw) {
    int blk = blockIdx.x;
    int b = blk / (NBOX * NHD);
    int n = (blk / NHD) % NBOX;
    int hg = thw[1], wg = thw[2];
    const float* bx = boxes + (long)(b * NBOX + n) * 4;
    float x1 = bx[0], y1 = bx[1], x2 = bx[2], y2 = bx[3];
    int px1 = min(max((int)floorf(x1 * (float)wg), 0), wg - 1);
    int px2 = max(px1 + 1, min((int)floorf(x2 * (float)wg), wg));
    int py1 = min(max((int)floorf(y1 * (float)hg), 0), hg - 1);
    int py2 = max(py1 + 1, min((int)floorf(y2 * (float)hg), hg));

    float* row = scores + (long)blk * NPATCH;
    __shared__ float sh[NPATCH];
    __shared__ float red[TPB];
    int tid = threadIdx.x;
    int hw = hg * wg;

    float mx = -1e30f;
    for (int i = tid; i < NPATCH; i += TPB) {
        int q = i % hw;
        int rr = q / wg, cc = q % wg;
        bool in = (rr >= py1) && (rr < py2) && (cc >= px1) && (cc < px2);
        float v = in ? row[i] : -1e30f;
        sh[i] = v;
        mx = fmaxf(mx, v);
    }
    red[tid] = mx;
    __syncthreads();
    for (int s = TPB / 2; s > 0; s >>= 1) {
        if (tid < s) red[tid] = fmaxf(red[tid], red[tid + s]);
        __syncthreads();
    }
    float maxv = red[0];
    __syncthreads();

    float sum = 0.f;
    for (int i = tid; i < NPATCH; i += TPB) {
        float e = expf(sh[i] - maxv);
        sh[i] = e;
        sum += e;
    }
    red[tid] = sum;
    __syncthreads();
    for (int s = TPB / 2; s > 0; s >>= 1) {
        if (tid < s) red[tid] += red[tid + s];
        __syncthreads();
    }
    float inv = 1.f / red[0];
    __syncthreads();
    for (int i = tid; i < NPATCH; i += TPB) row[i] = sh[i] * inv;
}

// ------------------------- layernorm -----------------------------------------
__global__ void ln_kernel(const float* __restrict__ gamma, const float* __restrict__ beta) {
    int r = blockIdx.x;
    const float* x = g_comb + (long)r * DIM;
    __shared__ float red[TPB];
    __shared__ float red2[TPB];
    int tid = threadIdx.x;
    float s = 0.f, s2 = 0.f;
    for (int i = tid; i < DIM; i += TPB) {
        float v = x[i];
        s += v;
        s2 += v * v;
    }
    red[tid] = s; red2[tid] = s2;
    __syncthreads();
    for (int st = TPB / 2; st > 0; st >>= 1) {
        if (tid < st) { red[tid] += red[tid + st]; red2[tid] += red2[tid + st]; }
        __syncthreads();
    }
    float mu = red[0] / DIM;
    float var = red2[0] / DIM - mu * mu;
    float inv = rsqrtf(var + 1e-5f);
    for (int i = tid; i < DIM; i += TPB)
        g_ln[(long)r * DIM + i] = (x[i] - mu) * inv * gamma[i] + beta[i];
}

// ------------------------- launch --------------------------------------------
extern "C" void kernel_launch(void* const* d_in, const int* in_sizes, int n_in,
                              void* d_out, int out_size) {
    const float*         emb   = (const float*)d_in[0];
    const int*           ids   = (const int*)d_in[1];
    const unsigned char* msk   = (const unsigned char*)d_in[2];
    const float*         boxes = (const float*)d_in[3];
    const int*           thw   = (const int*)d_in[4];
    const int*           tok   = (const int*)d_in[5];
    const float*         Win   = (const float*)d_in[6];
    const float*         bin   = (const float*)d_in[7];
    const float*         Wout  = (const float*)d_in[8];
    const float*         bout  = (const float*)d_in[9];
    const float*         gam   = (const float*)d_in[10];
    const float*         bet   = (const float*)d_in[11];
    const float*         W1    = (const float*)d_in[12];
    const float*         b1    = (const float*)d_in[13];
    const float*         W2    = (const float*)d_in[14];
    const float*         b2    = (const float*)d_in[15];
    float*               out   = (float*)d_out;

    const float* Wq = Win;
    const float* Wk = Win + (long)DIM * DIM;
    const float* Wv = Win + 2L * DIM * DIM;
    const float* bv = bin + 2L * DIM;

    float *qtok, *q, *qk, *scores, *u, *ctx, *comb, *ln, *hidden, *rows, *part;
    int *start;
    cudaGetSymbolAddress((void**)&qtok,   g_qtok);
    cudaGetSymbolAddress((void**)&q,      g_q);
    cudaGetSymbolAddress((void**)&qk,     g_qk);
    cudaGetSymbolAddress((void**)&scores, g_scores);
    cudaGetSymbolAddress((void**)&u,      g_u);
    cudaGetSymbolAddress((void**)&ctx,    g_ctx);
    cudaGetSymbolAddress((void**)&comb,   g_comb);
    cudaGetSymbolAddress((void**)&ln,     g_ln);
    cudaGetSymbolAddress((void**)&hidden, g_hidden);
    cudaGetSymbolAddress((void**)&rows,   g_rows);
    cudaGetSymbolAddress((void**)&part,   g_part);
    cudaGetSymbolAddress((void**)&start,  g_start);

    const float scale = 1.0f / sqrtf((float)DHD);
    const long n4 = (long)BATCH * SEQ * DIM / 4;

    // 1. output base copy
    copy_kernel<<<8192, TPB>>>((const float4*)emb, (float4*)out, n4);
    // 2. positions + patch start
    scan_kernel<<<BATCH, TPB>>>(ids, msk, tok);
    // 3. gather query tokens
    gather_kernel<<<NTOK, TPB>>>(emb);

    // 4. q = (qtok @ Wq^T + bq) * scale   SK=28 (Kc=128)
    skinny_tb<<<dim3(14, 28, 1), TPB>>>(qtok, DIM, 0, Wq, DIM, 0, part, DIM, DIM, 28);
    combine_kernel<<<(NTOK * DIM + TPB - 1) / TPB, TPB>>>(
        part, 28, q, DIM, 0, NTOK, DIM, bin, 0, nullptr, 0, scale, 0, NTOK * DIM);

    // 5. qk[t,h,:] = q[t,h,:] @ Wk_h   (NN), SK=8
    skinny_nn<<<dim3(4, 8, NHD), TPB>>>(q, DIM, DHD, Wk, DIM, (long)DHD * DIM,
                                        part, DIM, DHD, 8);
    combine_kernel<<<(NHD * NTOK * DIM + TPB - 1) / TPB, TPB>>>(
        part, 8, qk, NHD * DIM, DIM, NTOK, DIM, nullptr, 0, nullptr, 0, 1.f, 0,
        NHD * NTOK * DIM);

    // 6. scores = qk @ patches^T   (tf32 mma, SK=4, 512 blocks)
    mma_gemm<true><<<dim3(NPATCH / 64, 4, BATCH), TPB>>>(
        qk, (long)96 * DIM, emb, (long)SEQ * DIM,
        part, NPATCH, DIM, 4, start);
    combine_kernel<<<(BATCH * 96 * NPATCH + TPB - 1) / TPB, TPB>>>(
        part, 4, scores, NPATCH, (long)96 * NPATCH, 96, NPATCH,
        nullptr, 0, nullptr, 0, 1.f, 0, BATCH * 96 * NPATCH);

    // 7. masked softmax
    softmax_kernel<<<BATCH * NBOX * NHD, TPB>>>(scores, boxes, thw);

    // 8. u = attn @ patches   (tf32 mma, SK=4, 448 blocks)
    mma_gemm<false><<<dim3(DIM / 64, 4, BATCH), TPB>>>(
        scores, (long)96 * NPATCH, emb, (long)SEQ * DIM,
        part, DIM, NPATCH, 4, start);
    combine_kernel<<<(BATCH * 96 * DIM + TPB - 1) / TPB, TPB>>>(
        part, 4, u, DIM, (long)96 * DIM, 96, DIM,
        nullptr, 0, nullptr, 0, 1.f, 0, BATCH * 96 * DIM);

    // 9. ctx[:, h] = u_h @ Wv_h^T + bv_h   SK=28
    skinny_tb<<<dim3(2, 28, NHD), TPB>>>(u, NHD * DIM, DIM, Wv, DIM, (long)DHD * DIM,
                                         part, DHD, DIM, 28);
    combine_kernel<<<(NHD * NTOK * DHD + TPB - 1) / TPB, TPB>>>(
        part, 28, ctx, DIM, DHD, NTOK, DHD, bv, DHD, nullptr, 0, 1.f, 0,
        NHD * NTOK * DHD);

    // 10. combined = ctx @ Wout^T + bout + qtok   SK=28
    skinny_tb<<<dim3(14, 28, 1), TPB>>>(ctx, DIM, 0, Wout, DIM, 0, part, DIM, DIM, 28);
    combine_kernel<<<(NTOK * DIM + TPB - 1) / TPB, TPB>>>(
        part, 28, comb, DIM, 0, NTOK, DIM, bout, 0, qtok, 0, 1.f, 0, NTOK * DIM);

    // 11. layernorm
    ln_kernel<<<NTOK, TPB>>>(gam, bet);

    // 12. hidden = gelu(ln @ W1^T + b1)   SK=28
    skinny_tb<<<dim3(28, 28, 1), TPB>>>(ln, DIM, 0, W1, DIM, 0, part, DFF, DIM, 28);
    combine_kernel<<<(NTOK * DFF + TPB - 1) / TPB, TPB>>>(
        part, 28, hidden, DFF, 0, NTOK, DFF, b1, 0, nullptr, 0, 1.f, 1, NTOK * DFF);

    // 13. rows = ln + hidden @ W2^T + b2   SK=56
    skinny_tb<<<dim3(14, 56, 1), TPB>>>(hidden, DFF, 0, W2, DFF, 0, part, DIM, DFF, 56);
    combine_kernel<<<(NTOK * DIM + TPB - 1) / TPB, TPB>>>(
        part, 56, rows, DIM, 0, NTOK, DIM, b2, 0, ln, 0, 1.f, 0, NTOK * DIM);

    // 14. scatter
    scatter_kernel<<<NTOK, TPB>>>(out);
}

// round 6
// speedup vs baseline: 2.8506x; 1.3596x over previous
#include <cuda_runtime.h>
#include <math.h>

#define BATCH   2
#define SEQ     4608
#define DIM     3584
#define NHD     8
#define DHD     448
#define NPATCH  4096
#define NBOX    12
#define DFF     7168
#define NTOK    24
#define TPB     256

// ------------------------- scratch ------------------------------------------
__device__ int   g_pos[NTOK];
__device__ int   g_start[BATCH];
__device__ float g_qtok[NTOK * DIM];
__device__ float g_q[NTOK * DIM];
__device__ float g_qk[NTOK * NHD * DIM];
__device__ float g_scores[BATCH * NBOX * NHD * NPATCH];
__device__ float g_u[NTOK * NHD * DIM];
__device__ float g_ctx[NTOK * DIM];
__device__ float g_comb[NTOK * DIM];
__device__ float g_ln[NTOK * DIM];
__device__ float g_hidden[NTOK * DFF];
__device__ float g_rows[NTOK * DIM];
__device__ float g_part[5505024];          // split-K partial scratch (22 MB)

// ------------------------- simple kernels ------------------------------------
__global__ void copy_kernel(const float4* __restrict__ src, float4* __restrict__ dst, long n4) {
    long i = (long)blockIdx.x * blockDim.x + threadIdx.x;
    long stride = (long)gridDim.x * blockDim.x;
    for (; i < n4; i += stride) dst[i] = src[i];
}

__global__ void scan_kernel(const int* __restrict__ ids,
                            const unsigned char* __restrict__ mask,
                            const int* __restrict__ tokPtr) {
    int b = blockIdx.x;
    __shared__ int sh[SEQ];
    __shared__ int s_f0, s_es, s_off, s_first;
    int tid = threadIdx.x;

    if (tid == 0) s_f0 = 0x7fffffff;
    __syncthreads();
    for (int i = tid; i < SEQ; i += blockDim.x) {
        if (mask[i] != 0) { atomicMin(&s_f0, i); break; }
    }
    __syncthreads();
    if (tid == 0) {
        int f0 = s_f0;
        unsigned char b0 = mask[f0];
        unsigned char b1 = mask[f0 + 1];
        if (b0 == 1u && b1 == 0u)      { s_es = 4; s_off = 0; }
        else if (b0 == 0x80u)          { s_es = 4; s_off = 2; }
        else                           { s_es = 1; s_off = 0; }
        s_first = SEQ;
    }
    __syncthreads();
    int es = s_es, off = s_off;
    for (int i = tid; i < SEQ; i += blockDim.x)
        if (mask[((long)b * SEQ + i) * es + off] != 0) atomicMin(&s_first, i);
    __syncthreads();
    if (tid == 0) g_start[b] = s_first;

    for (int i = tid; i < SEQ; i += blockDim.x)
        sh[i] = ids[(long)b * SEQ + i];
    __syncthreads();
    if (tid < 32) {
        int tok = *tokPtr;
        int count = 0;
        for (int base = 0; base < SEQ && count < NBOX; base += 32) {
            unsigned bal = __ballot_sync(0xffffffffu, sh[base + tid] == tok);
            while (bal && count < NBOX) {
                int o = __ffs(bal) - 1;
                if (tid == 0) g_pos[b * NBOX + count] = base + o;
                count++;
                bal &= bal - 1;
            }
        }
    }
}

__global__ void gather_kernel(const float* __restrict__ emb) {
    int r = blockIdx.x;
    int b = r / NBOX;
    const float* src = emb + ((long)b * SEQ + g_pos[r]) * DIM;
    for (int i = threadIdx.x; i < DIM; i += blockDim.x) g_qtok[(long)r * DIM + i] = src[i];
}

__global__ void scatter_kernel(float* __restrict__ out) {
    int r = blockIdx.x;
    int b = r / NBOX;
    float* dst = out + ((long)b * SEQ + g_pos[r]) * DIM;
    for (int i = threadIdx.x; i < DIM; i += blockDim.x) dst[i] = g_rows[(long)r * DIM + i];
}

// ------------------------- skinny tf32 mma GEMM ------------------------------
// C[24,N] = A[24,K] @ (TB ? W[n,k]^T : W[k,n]).  M padded to 32 with zeros.
// BM=32, BN=128, BK=32. 8 warps, each covers m32 x n16. Split-K partials
// written as P[(z*SK+s)*24 + m][N].
template<bool TB>
__global__ __launch_bounds__(TPB) void skinny_mma(
    const float* __restrict__ A, int lda, long Az,
    const float* __restrict__ W, int ldw, long Wz,
    float* __restrict__ P, int N, int K, int SK)
{
    const int z = blockIdx.z, s = blockIdx.y;
    const int n0 = blockIdx.x * 128;
    const int Kc = K / SK;
    const int kBeg = s * Kc;
    A += (long)z * Az;
    W += (long)z * Wz;

    __shared__ float Asm[32 * 36];
    __shared__ float Bs[128 * 36];      // TB: [n][36]; NN: [k][136] (4352 < 4608)

    const int tid  = threadIdx.x;
    const int wid  = tid >> 5;
    const int lane = tid & 31;
    const int grp  = lane >> 2;
    const int th   = lane & 3;

    float c[2][2][4];
#pragma unroll
    for (int i = 0; i < 2; i++)
#pragma unroll
        for (int j = 0; j < 2; j++)
#pragma unroll
            for (int r = 0; r < 4; r++) c[i][j][r] = 0.f;

    const int nTiles = Kc / 32;
    for (int t = 0; t < nTiles; t++) {
        const int k0 = kBeg + t * 32;
        // A tile 32x32 (rows >= 24 zero)
        {
            int m = tid >> 3, kc = tid & 7;
            float4 v = make_float4(0, 0, 0, 0);
            if (m < NTOK)
                v = *reinterpret_cast<const float4*>(A + (long)m * lda + k0 + kc * 4);
            float* d = &Asm[m * 36 + kc * 4];
            d[0] = v.x; d[1] = v.y; d[2] = v.z; d[3] = v.w;
        }
        // B tile
        if (TB) {
#pragma unroll
            for (int it = 0; it < 4; it++) {
                int idx = tid + it * TPB;
                int nn = idx >> 3, kc = idx & 7;
                float4 v = make_float4(0, 0, 0, 0);
                if (n0 + nn < N)
                    v = *reinterpret_cast<const float4*>(W + (long)(n0 + nn) * ldw + k0 + kc * 4);
                float* d = &Bs[nn * 36 + kc * 4];
                d[0] = v.x; d[1] = v.y; d[2] = v.z; d[3] = v.w;
            }
        } else {
#pragma unroll
            for (int it = 0; it < 4; it++) {
                int idx = tid + it * TPB;
                int kk = idx >> 5, nc = idx & 31;
                float4 v = make_float4(0, 0, 0, 0);
                if (n0 + nc * 4 < N)
                    v = *reinterpret_cast<const float4*>(W + (long)(k0 + kk) * ldw + n0 + nc * 4);
                float* d = &Bs[kk * 136 + nc * 4];
                d[0] = v.x; d[1] = v.y; d[2] = v.z; d[3] = v.w;
            }
        }
        __syncthreads();

#pragma unroll
        for (int q = 0; q < 32; q += 8) {
            unsigned a[2][4], b[2][2];
#pragma unroll
            for (int mt = 0; mt < 2; mt++) {
                int row = mt * 16 + grp;
                const unsigned* ap  = reinterpret_cast<const unsigned*>(&Asm[row * 36 + q + th]);
                const unsigned* ap8 = reinterpret_cast<const unsigned*>(&Asm[(row + 8) * 36 + q + th]);
                a[mt][0] = ap[0];
                a[mt][1] = ap8[0];
                a[mt][2] = ap[4];
                a[mt][3] = ap8[4];
            }
#pragma unroll
            for (int fn = 0; fn < 2; fn++) {
                int col = wid * 16 + fn * 8 + grp;
                if (TB) {
                    const unsigned* bp = reinterpret_cast<const unsigned*>(&Bs[col * 36 + q + th]);
                    b[fn][0] = bp[0];
                    b[fn][1] = bp[4];
                } else {
                    b[fn][0] = reinterpret_cast<const unsigned*>(&Bs[(q + th) * 136 + col])[0];
                    b[fn][1] = reinterpret_cast<const unsigned*>(&Bs[(q + th + 4) * 136 + col])[0];
                }
            }
#pragma unroll
            for (int mt = 0; mt < 2; mt++)
#pragma unroll
                for (int fn = 0; fn < 2; fn++) {
                    asm volatile(
                        "mma.sync.aligned.m16n8k8.row.col.f32.tf32.tf32.f32 "
                        "{%0,%1,%2,%3}, {%4,%5,%6,%7}, {%8,%9}, {%0,%1,%2,%3};"
                        : "+f"(c[mt][fn][0]), "+f"(c[mt][fn][1]),
                          "+f"(c[mt][fn][2]), "+f"(c[mt][fn][3])
                        : "r"(a[mt][0]), "r"(a[mt][1]), "r"(a[mt][2]), "r"(a[mt][3]),
                          "r"(b[fn][0]), "r"(b[fn][1]));
                }
        }
        __syncthreads();
    }

    long base = (long)(z * SK + s) * NTOK * N;
#pragma unroll
    for (int mt = 0; mt < 2; mt++) {
        int r0 = mt * 16 + grp;
#pragma unroll
        for (int fn = 0; fn < 2; fn++) {
            int col = n0 + wid * 16 + fn * 8 + th * 2;
            if (col < N) {
                *reinterpret_cast<float2*>(&P[base + (long)r0 * N + col]) =
                    make_float2(c[mt][fn][0], c[mt][fn][1]);
                if (mt == 0)
                    *reinterpret_cast<float2*>(&P[base + (long)(r0 + 8) * N + col]) =
                        make_float2(c[mt][fn][2], c[mt][fn][3]);
            }
        }
    }
}

// ------------------------- big tf32 mma GEMM (M=96) --------------------------
template<bool TB>
__global__ __launch_bounds__(TPB) void mma_gemm(
    const float* __restrict__ A, long Az,
    const float* __restrict__ B, long Bz,
    float* __restrict__ P, int N, int K, int SK,
    const int* __restrict__ patchStart)
{
    const int z = blockIdx.z, s = blockIdx.y;
    const int n0 = blockIdx.x * 64;
    const int kLen = K / SK;
    const int kBeg = s * kLen;
    A += (long)z * Az;
    B += (long)z * Bz + (long)patchStart[z] * DIM;

    __shared__ float Asm[96 * 36];
    __shared__ float Bs[2304];

    const int tid  = threadIdx.x;
    const int wid  = tid >> 5;
    const int lane = tid & 31;
    const int grp  = lane >> 2;
    const int th   = lane & 3;
    const int warpM = wid >> 2;
    const int warpN = wid & 3;

    float c[3][2][4];
#pragma unroll
    for (int i = 0; i < 3; i++)
#pragma unroll
        for (int j = 0; j < 2; j++)
#pragma unroll
            for (int r = 0; r < 4; r++) c[i][j][r] = 0.f;

    const int nTiles = kLen / 32;
    for (int t = 0; t < nTiles; t++) {
        const int k0 = kBeg + t * 32;
#pragma unroll
        for (int it = 0; it < 3; it++) {
            int idx = tid + it * TPB;
            int m = idx >> 3, kc = idx & 7;
            float4 v = *reinterpret_cast<const float4*>(A + (long)m * K + k0 + kc * 4);
            float* d = &Asm[m * 36 + kc * 4];
            d[0] = v.x; d[1] = v.y; d[2] = v.z; d[3] = v.w;
        }
        if (TB) {
#pragma unroll
            for (int it = 0; it < 2; it++) {
                int idx = tid + it * TPB;
                int nn = idx >> 3, kc = idx & 7;
                float4 v = *reinterpret_cast<const float4*>(B + (long)(n0 + nn) * DIM + k0 + kc * 4);
                float* d = &Bs[nn * 36 + kc * 4];
                d[0] = v.x; d[1] = v.y; d[2] = v.z; d[3] = v.w;
            }
        } else {
#pragma unroll
            for (int it = 0; it < 2; it++) {
                int idx = tid + it * TPB;
                int kk = idx >> 4, nc = idx & 15;
                float4 v = *reinterpret_cast<const float4*>(B + (long)(k0 + kk) * DIM + n0 + nc * 4);
                float* d = &Bs[kk * 72 + nc * 4];
                d[0] = v.x; d[1] = v.y; d[2] = v.z; d[3] = v.w;
            }
        }
        __syncthreads();

#pragma unroll
        for (int q = 0; q < 32; q += 8) {
            unsigned a[3][4], b[2][2];
#pragma unroll
            for (int fr = 0; fr < 3; fr++) {
                int row = warpM * 48 + fr * 16 + grp;
                const unsigned* ap  = reinterpret_cast<const unsigned*>(&Asm[row * 36 + q + th]);
                const unsigned* ap8 = reinterpret_cast<const unsigned*>(&Asm[(row + 8) * 36 + q + th]);
                a[fr][0] = ap[0];
                a[fr][1] = ap8[0];
                a[fr][2] = ap[4];
                a[fr][3] = ap8[4];
            }
#pragma unroll
            for (int fn = 0; fn < 2; fn++) {
                int col = warpN * 16 + fn * 8 + grp;
                if (TB) {
                    const unsigned* bp = reinterpret_cast<const unsigned*>(&Bs[col * 36 + q + th]);
                    b[fn][0] = bp[0];
                    b[fn][1] = bp[4];
                } else {
                    b[fn][0] = reinterpret_cast<const unsigned*>(&Bs[(q + th) * 72 + col])[0];
                    b[fn][1] = reinterpret_cast<const unsigned*>(&Bs[(q + th + 4) * 72 + col])[0];
                }
            }
#pragma unroll
            for (int fr = 0; fr < 3; fr++)
#pragma unroll
                for (int fn = 0; fn < 2; fn++) {
                    asm volatile(
                        "mma.sync.aligned.m16n8k8.row.col.f32.tf32.tf32.f32 "
                        "{%0,%1,%2,%3}, {%4,%5,%6,%7}, {%8,%9}, {%0,%1,%2,%3};"
                        : "+f"(c[fr][fn][0]), "+f"(c[fr][fn][1]),
                          "+f"(c[fr][fn][2]), "+f"(c[fr][fn][3])
                        : "r"(a[fr][0]), "r"(a[fr][1]), "r"(a[fr][2]), "r"(a[fr][3]),
                          "r"(b[fn][0]), "r"(b[fn][1]));
                }
        }
        __syncthreads();
    }

    long base = (long)(z * SK + s) * 96 * N;
#pragma unroll
    for (int fr = 0; fr < 3; fr++) {
        int r0 = warpM * 48 + fr * 16 + grp;
#pragma unroll
        for (int fn = 0; fn < 2; fn++) {
            int col = n0 + warpN * 16 + fn * 8 + th * 2;
            *reinterpret_cast<float2*>(&P[base + (long)r0 * N + col]) =
                make_float2(c[fr][fn][0], c[fr][fn][1]);
            *reinterpret_cast<float2*>(&P[base + (long)(r0 + 8) * N + col]) =
                make_float2(c[fr][fn][2], c[fr][fn][3]);
        }
    }
}

// reduce split-K partials + epilogue
__global__ void combine_kernel(const float* __restrict__ P, int SK,
                               float* __restrict__ C, int ldc, long Cz, int M, int N,
                               const float* __restrict__ bias, long biasZ,
                               const float* __restrict__ resid, long residZ,
                               float scale, int act, int total) {
    int idx = blockIdx.x * blockDim.x + threadIdx.x;
    if (idx >= total) return;
    int n = idx % N;
    int t = idx / N;
    int m = t % M;
    int z = t / M;
    float v = 0.f;
    for (int s = 0; s < SK; s++) v += P[((long)(z * SK + s) * M + m) * N + n];
    if (bias)  v += bias[z * biasZ + n];
    v *= scale;
    if (act)   v = v * normcdff(v);
    if (resid) v += resid[z * residZ + (long)m * ldc + n];
    C[z * Cz + (long)m * ldc + n] = v;
}

// ------------------------- masked softmax ------------------------------------
__global__ void softmax_kernel(float* __restrict__ scores,
                               const float* __restrict__ boxes,
                               const int* __restrict__ thw) {
    int blk = blockIdx.x;
    int b = blk / (NBOX * NHD);
    int n = (blk / NHD) % NBOX;
    int hg = thw[1], wg = thw[2];
    const float* bx = boxes + (long)(b * NBOX + n) * 4;
    float x1 = bx[0], y1 = bx[1], x2 = bx[2], y2 = bx[3];
    int px1 = min(max((int)floorf(x1 * (float)wg), 0), wg - 1);
    int px2 = max(px1 + 1, min((int)floorf(x2 * (float)wg), wg));
    int py1 = min(max((int)floorf(y1 * (float)hg), 0), hg - 1);
    int py2 = max(py1 + 1, min((int)floorf(y2 * (float)hg), hg));

    float* row = scores + (long)blk * NPATCH;
    __shared__ float sh[NPATCH];
    __shared__ float red[TPB];
    int tid = threadIdx.x;
    int hw = hg * wg;

    float mx = -1e30f;
    for (int i = tid; i < NPATCH; i += TPB) {
        int q = i % hw;
        int rr = q / wg, cc = q % wg;
        bool in = (rr >= py1) && (rr < py2) && (cc >= px1) && (cc < px2);
        float v = in ? row[i] : -1e30f;
        sh[i] = v;
        mx = fmaxf(mx, v);
    }
    red[tid] = mx;
    __syncthreads();
    for (int s = TPB / 2; s > 0; s >>= 1) {
        if (tid < s) red[tid] = fmaxf(red[tid], red[tid + s]);
        __syncthreads();
    }
    float maxv = red[0];
    __syncthreads();

    float sum = 0.f;
    for (int i = tid; i < NPATCH; i += TPB) {
        float e = expf(sh[i] - maxv);
        sh[i] = e;
        sum += e;
    }
    red[tid] = sum;
    __syncthreads();
    for (int s = TPB / 2; s > 0; s >>= 1) {
        if (tid < s) red[tid] += red[tid + s];
        __syncthreads();
    }
    float inv = 1.f / red[0];
    __syncthreads();
    for (int i = tid; i < NPATCH; i += TPB) row[i] = sh[i] * inv;
}

// ------------------------- layernorm -----------------------------------------
__global__ void ln_kernel(const float* __restrict__ gamma, const float* __restrict__ beta) {
    int r = blockIdx.x;
    const float* x = g_comb + (long)r * DIM;
    __shared__ float red[TPB];
    __shared__ float red2[TPB];
    int tid = threadIdx.x;
    float s = 0.f, s2 = 0.f;
    for (int i = tid; i < DIM; i += TPB) {
        float v = x[i];
        s += v;
        s2 += v * v;
    }
    red[tid] = s; red2[tid] = s2;
    __syncthreads();
    for (int st = TPB / 2; st > 0; st >>= 1) {
        if (tid < st) { red[tid] += red[tid + st]; red2[tid] += red2[tid + st]; }
        __syncthreads();
    }
    float mu = red[0] / DIM;
    float var = red2[0] / DIM - mu * mu;
    float inv = rsqrtf(var + 1e-5f);
    for (int i = tid; i < DIM; i += TPB)
        g_ln[(long)r * DIM + i] = (x[i] - mu) * inv * gamma[i] + beta[i];
}

// ------------------------- launch --------------------------------------------
extern "C" void kernel_launch(void* const* d_in, const int* in_sizes, int n_in,
                              void* d_out, int out_size) {
    const float*         emb   = (const float*)d_in[0];
    const int*           ids   = (const int*)d_in[1];
    const unsigned char* msk   = (const unsigned char*)d_in[2];
    const float*         boxes = (const float*)d_in[3];
    const int*           thw   = (const int*)d_in[4];
    const int*           tok   = (const int*)d_in[5];
    const float*         Win   = (const float*)d_in[6];
    const float*         bin   = (const float*)d_in[7];
    const float*         Wout  = (const float*)d_in[8];
    const float*         bout  = (const float*)d_in[9];
    const float*         gam   = (const float*)d_in[10];
    const float*         bet   = (const float*)d_in[11];
    const float*         W1    = (const float*)d_in[12];
    const float*         b1    = (const float*)d_in[13];
    const float*         W2    = (const float*)d_in[14];
    const float*         b2    = (const float*)d_in[15];
    float*               out   = (float*)d_out;

    const float* Wq = Win;
    const float* Wk = Win + (long)DIM * DIM;
    const float* Wv = Win + 2L * DIM * DIM;
    const float* bv = bin + 2L * DIM;

    float *qtok, *q, *qk, *scores, *u, *ctx, *comb, *ln, *hidden, *rows, *part;
    int *start;
    cudaGetSymbolAddress((void**)&qtok,   g_qtok);
    cudaGetSymbolAddress((void**)&q,      g_q);
    cudaGetSymbolAddress((void**)&qk,     g_qk);
    cudaGetSymbolAddress((void**)&scores, g_scores);
    cudaGetSymbolAddress((void**)&u,      g_u);
    cudaGetSymbolAddress((void**)&ctx,    g_ctx);
    cudaGetSymbolAddress((void**)&comb,   g_comb);
    cudaGetSymbolAddress((void**)&ln,     g_ln);
    cudaGetSymbolAddress((void**)&hidden, g_hidden);
    cudaGetSymbolAddress((void**)&rows,   g_rows);
    cudaGetSymbolAddress((void**)&part,   g_part);
    cudaGetSymbolAddress((void**)&start,  g_start);

    const float scale = 1.0f / sqrtf((float)DHD);
    const long n4 = (long)BATCH * SEQ * DIM / 4;

    // 1. output base copy
    copy_kernel<<<8192, TPB>>>((const float4*)emb, (float4*)out, n4);
    // 2. positions + patch start
    scan_kernel<<<BATCH, TPB>>>(ids, msk, tok);
    // 3. gather query tokens
    gather_kernel<<<NTOK, TPB>>>(emb);

    // 4. q = (qtok @ Wq^T + bq) * scale   (mma TB, SK=16, Kc=224, grid 448)
    skinny_mma<true><<<dim3(28, 16, 1), TPB>>>(qtok, DIM, 0, Wq, DIM, 0, part, DIM, DIM, 16);
    combine_kernel<<<(NTOK * DIM + TPB - 1) / TPB, TPB>>>(
        part, 16, q, DIM, 0, NTOK, DIM, bin, 0, nullptr, 0, scale, 0, NTOK * DIM);

    // 5. qk[t,h,:] = q[t,h,:] @ Wk_h   (mma NN per head, SK=2, Kc=224, grid 448)
    skinny_mma<false><<<dim3(28, 2, NHD), TPB>>>(q, DIM, DHD, Wk, DIM, (long)DHD * DIM,
                                                 part, DIM, DHD, 2);
    combine_kernel<<<(NHD * NTOK * DIM + TPB - 1) / TPB, TPB>>>(
        part, 2, qk, NHD * DIM, DIM, NTOK, DIM, nullptr, 0, nullptr, 0, 1.f, 0,
        NHD * NTOK * DIM);

    // 6. scores = qk @ patches^T   (tf32 mma, SK=4, 512 blocks)
    mma_gemm<true><<<dim3(NPATCH / 64, 4, BATCH), TPB>>>(
        qk, (long)96 * DIM, emb, (long)SEQ * DIM,
        part, NPATCH, DIM, 4, start);
    combine_kernel<<<(BATCH * 96 * NPATCH + TPB - 1) / TPB, TPB>>>(
        part, 4, scores, NPATCH, (long)96 * NPATCH, 96, NPATCH,
        nullptr, 0, nullptr, 0, 1.f, 0, BATCH * 96 * NPATCH);

    // 7. masked softmax
    softmax_kernel<<<BATCH * NBOX * NHD, TPB>>>(scores, boxes, thw);

    // 8. u = attn @ patches   (tf32 mma, SK=4, 448 blocks)
    mma_gemm<false><<<dim3(DIM / 64, 4, BATCH), TPB>>>(
        scores, (long)96 * NPATCH, emb, (long)SEQ * DIM,
        part, DIM, NPATCH, 4, start);
    combine_kernel<<<(BATCH * 96 * DIM + TPB - 1) / TPB, TPB>>>(
        part, 4, u, DIM, (long)96 * DIM, 96, DIM,
        nullptr, 0, nullptr, 0, 1.f, 0, BATCH * 96 * DIM);

    // 9. ctx[:, h] = u_h @ Wv_h^T + bv_h   (mma TB per head, SK=16, Kc=224, grid 512)
    skinny_mma<true><<<dim3(4, 16, NHD), TPB>>>(u, NHD * DIM, DIM, Wv, DIM, (long)DHD * DIM,
                                                part, DHD, DIM, 16);
    combine_kernel<<<(NHD * NTOK * DHD + TPB - 1) / TPB, TPB>>>(
        part, 16, ctx, DIM, DHD, NTOK, DHD, bv, DHD, nullptr, 0, 1.f, 0,
        NHD * NTOK * DHD);

    // 10. combined = ctx @ Wout^T + bout + qtok   (mma TB, SK=16)
    skinny_mma<true><<<dim3(28, 16, 1), TPB>>>(ctx, DIM, 0, Wout, DIM, 0, part, DIM, DIM, 16);
    combine_kernel<<<(NTOK * DIM + TPB - 1) / TPB, TPB>>>(
        part, 16, comb, DIM, 0, NTOK, DIM, bout, 0, qtok, 0, 1.f, 0, NTOK * DIM);

    // 11. layernorm
    ln_kernel<<<NTOK, TPB>>>(gam, bet);

    // 12. hidden = gelu(ln @ W1^T + b1)   (mma TB, SK=8, Kc=448, grid 448)
    skinny_mma<true><<<dim3(56, 8, 1), TPB>>>(ln, DIM, 0, W1, DIM, 0, part, DFF, DIM, 8);
    combine_kernel<<<(NTOK * DFF + TPB - 1) / TPB, TPB>>>(
        part, 8, hidden, DFF, 0, NTOK, DFF, b1, 0, nullptr, 0, 1.f, 1, NTOK * DFF);

    // 13. rows = ln + hidden @ W2^T + b2   (mma TB, SK=16, Kc=448, grid 448)
    skinny_mma<true><<<dim3(28, 16, 1), TPB>>>(hidden, DFF, 0, W2, DFF, 0, part, DIM, DFF, 16);
    combine_kernel<<<(NTOK * DIM + TPB - 1) / TPB, TPB>>>(
        part, 16, rows, DIM, 0, NTOK, DIM, b2, 0, ln, 0, 1.f, 0, NTOK * DIM);

    // 14. scatter
    scatter_kernel<<<NTOK, TPB>>>(out);
}

// round 7
// speedup vs baseline: 3.3505x; 1.1754x over previous
#include <cuda_runtime.h>
#include <math.h>

#define BATCH   2
#define SEQ     4608
#define DIM     3584
#define NHD     8
#define DHD     448
#define NPATCH  4096
#define NBOX    12
#define DFF     7168
#define NTOK    24
#define TPB     256

// ------------------------- scratch ------------------------------------------
__device__ int   g_pos[NTOK];
__device__ int   g_start[BATCH];
__device__ float g_qtok[NTOK * DIM];
__device__ float g_q[NTOK * DIM];
__device__ float g_qk[NTOK * NHD * DIM];
__device__ float g_scores[BATCH * NBOX * NHD * NPATCH];
__device__ float g_u[NTOK * NHD * DIM];
__device__ float g_ctx[NTOK * DIM];
__device__ float g_comb[NTOK * DIM];
__device__ float g_ln[NTOK * DIM];
__device__ float g_hidden[NTOK * DFF];
__device__ float g_rows[NTOK * DIM];
__device__ float g_part[5505024];          // split-K partial scratch (22 MB)

// ------------------------- cp.async helpers ----------------------------------
__device__ __forceinline__ void cp16(void* smem, const void* gmem, bool pred) {
    unsigned sa = (unsigned)__cvta_generic_to_shared(smem);
    int sz = pred ? 16 : 0;
    asm volatile("cp.async.cg.shared.global [%0], [%1], 16, %2;\n"
                 :: "r"(sa), "l"(gmem), "r"(sz));
}
__device__ __forceinline__ void cp_commit() {
    asm volatile("cp.async.commit_group;\n");
}
template<int NWAIT>
__device__ __forceinline__ void cp_wait() {
    asm volatile("cp.async.wait_group %0;\n" :: "n"(NWAIT));
}

// ------------------------- simple kernels ------------------------------------
__global__ void copy_kernel(const float4* __restrict__ src, float4* __restrict__ dst, long n4) {
    long i = (long)blockIdx.x * blockDim.x + threadIdx.x;
    long stride = (long)gridDim.x * blockDim.x;
    for (; i < n4; i += stride) dst[i] = src[i];
}

__global__ void scan_kernel(const int* __restrict__ ids,
                            const unsigned char* __restrict__ mask,
                            const int* __restrict__ tokPtr) {
    int b = blockIdx.x;
    __shared__ int sh[SEQ];
    __shared__ int s_f0, s_es, s_off, s_first;
    int tid = threadIdx.x;

    if (tid == 0) s_f0 = 0x7fffffff;
    __syncthreads();
    for (int i = tid; i < SEQ; i += blockDim.x) {
        if (mask[i] != 0) { atomicMin(&s_f0, i); break; }
    }
    __syncthreads();
    if (tid == 0) {
        int f0 = s_f0;
        unsigned char b0 = mask[f0];
        unsigned char b1 = mask[f0 + 1];
        if (b0 == 1u && b1 == 0u)      { s_es = 4; s_off = 0; }
        else if (b0 == 0x80u)          { s_es = 4; s_off = 2; }
        else                           { s_es = 1; s_off = 0; }
        s_first = SEQ;
    }
    __syncthreads();
    int es = s_es, off = s_off;
    for (int i = tid; i < SEQ; i += blockDim.x)
        if (mask[((long)b * SEQ + i) * es + off] != 0) atomicMin(&s_first, i);
    __syncthreads();
    if (tid == 0) g_start[b] = s_first;

    for (int i = tid; i < SEQ; i += blockDim.x)
        sh[i] = ids[(long)b * SEQ + i];
    __syncthreads();
    if (tid < 32) {
        int tok = *tokPtr;
        int count = 0;
        for (int base = 0; base < SEQ && count < NBOX; base += 32) {
            unsigned bal = __ballot_sync(0xffffffffu, sh[base + tid] == tok);
            while (bal && count < NBOX) {
                int o = __ffs(bal) - 1;
                if (tid == 0) g_pos[b * NBOX + count] = base + o;
                count++;
                bal &= bal - 1;
            }
        }
    }
}

__global__ void gather_kernel(const float* __restrict__ emb) {
    int r = blockIdx.x;
    int b = r / NBOX;
    const float* src = emb + ((long)b * SEQ + g_pos[r]) * DIM;
    for (int i = threadIdx.x; i < DIM; i += blockDim.x) g_qtok[(long)r * DIM + i] = src[i];
}

__global__ void scatter_kernel(float* __restrict__ out) {
    int r = blockIdx.x;
    int b = r / NBOX;
    float* dst = out + ((long)b * SEQ + g_pos[r]) * DIM;
    for (int i = threadIdx.x; i < DIM; i += blockDim.x) dst[i] = g_rows[(long)r * DIM + i];
}

// ------------------------- skinny tf32 mma GEMM (double-buffered) ------------
// C[24,N] = A[24,K] @ (TB ? W[n,k]^T : W[k,n]).  M padded to 32 with zeros.
// BM=32, BN=128, BK=32. 8 warps each m32 x n16. Split-K partials.
template<bool TB>
__global__ __launch_bounds__(TPB) void skinny_mma(
    const float* __restrict__ A, int lda, long Az,
    const float* __restrict__ W, int ldw, long Wz,
    float* __restrict__ P, int N, int K, int SK)
{
    const int z = blockIdx.z, s = blockIdx.y;
    const int n0 = blockIdx.x * 128;
    const int Kc = K / SK;
    const int kBeg = s * Kc;
    A += (long)z * Az;
    W += (long)z * Wz;

    __shared__ float Asm[2][32 * 36];
    __shared__ float Bs[2][128 * 36];   // TB: [n][36]; NN: [k][136] (4352 < 4608)

    const int tid  = threadIdx.x;
    const int wid  = tid >> 5;
    const int lane = tid & 31;
    const int grp  = lane >> 2;
    const int th   = lane & 3;

    const int am = tid >> 3, akc = tid & 7;       // A loader coords

    auto load_tile = [&](int t, int buf) {
        const int k0 = kBeg + t * 32;
        cp16(&Asm[buf][am * 36 + akc * 4],
             A + (long)am * lda + k0 + akc * 4, am < NTOK);
        if (TB) {
#pragma unroll
            for (int it = 0; it < 4; it++) {
                int idx = tid + it * TPB;
                int nn = idx >> 3, kc = idx & 7;
                cp16(&Bs[buf][nn * 36 + kc * 4],
                     W + (long)(n0 + nn) * ldw + k0 + kc * 4, n0 + nn < N);
            }
        } else {
#pragma unroll
            for (int it = 0; it < 4; it++) {
                int idx = tid + it * TPB;
                int kk = idx >> 5, nc = idx & 31;
                cp16(&Bs[buf][kk * 136 + nc * 4],
                     W + (long)(k0 + kk) * ldw + n0 + nc * 4, n0 + nc * 4 < N);
            }
        }
        cp_commit();
    };

    float c[2][2][4];
#pragma unroll
    for (int i = 0; i < 2; i++)
#pragma unroll
        for (int j = 0; j < 2; j++)
#pragma unroll
            for (int r = 0; r < 4; r++) c[i][j][r] = 0.f;

    const int nTiles = Kc / 32;
    load_tile(0, 0);
    for (int t = 0; t < nTiles; t++) {
        const int buf = t & 1;
        if (t + 1 < nTiles) { load_tile(t + 1, buf ^ 1); cp_wait<1>(); }
        else                { cp_wait<0>(); }
        __syncthreads();

#pragma unroll
        for (int q = 0; q < 32; q += 8) {
            unsigned a[2][4], b[2][2];
#pragma unroll
            for (int mt = 0; mt < 2; mt++) {
                int row = mt * 16 + grp;
                const unsigned* ap  = reinterpret_cast<const unsigned*>(&Asm[buf][row * 36 + q + th]);
                const unsigned* ap8 = reinterpret_cast<const unsigned*>(&Asm[buf][(row + 8) * 36 + q + th]);
                a[mt][0] = ap[0];
                a[mt][1] = ap8[0];
                a[mt][2] = ap[4];
                a[mt][3] = ap8[4];
            }
#pragma unroll
            for (int fn = 0; fn < 2; fn++) {
                int col = wid * 16 + fn * 8 + grp;
                if (TB) {
                    const unsigned* bp = reinterpret_cast<const unsigned*>(&Bs[buf][col * 36 + q + th]);
                    b[fn][0] = bp[0];
                    b[fn][1] = bp[4];
                } else {
                    b[fn][0] = reinterpret_cast<const unsigned*>(&Bs[buf][(q + th) * 136 + col])[0];
                    b[fn][1] = reinterpret_cast<const unsigned*>(&Bs[buf][(q + th + 4) * 136 + col])[0];
                }
            }
#pragma unroll
            for (int mt = 0; mt < 2; mt++)
#pragma unroll
                for (int fn = 0; fn < 2; fn++) {
                    asm volatile(
                        "mma.sync.aligned.m16n8k8.row.col.f32.tf32.tf32.f32 "
                        "{%0,%1,%2,%3}, {%4,%5,%6,%7}, {%8,%9}, {%0,%1,%2,%3};"
                        : "+f"(c[mt][fn][0]), "+f"(c[mt][fn][1]),
                          "+f"(c[mt][fn][2]), "+f"(c[mt][fn][3])
                        : "r"(a[mt][0]), "r"(a[mt][1]), "r"(a[mt][2]), "r"(a[mt][3]),
                          "r"(b[fn][0]), "r"(b[fn][1]));
                }
        }
        __syncthreads();
    }

    long base = (long)(z * SK + s) * NTOK * N;
#pragma unroll
    for (int mt = 0; mt < 2; mt++) {
        int r0 = mt * 16 + grp;
#pragma unroll
        for (int fn = 0; fn < 2; fn++) {
            int col = n0 + wid * 16 + fn * 8 + th * 2;
            if (col < N) {
                *reinterpret_cast<float2*>(&P[base + (long)r0 * N + col]) =
                    make_float2(c[mt][fn][0], c[mt][fn][1]);
                if (mt == 0)
                    *reinterpret_cast<float2*>(&P[base + (long)(r0 + 8) * N + col]) =
                        make_float2(c[mt][fn][2], c[mt][fn][3]);
            }
        }
    }
}

// ------------------------- big tf32 mma GEMM (M=96, double-buffered) ---------
template<bool TB>
__global__ __launch_bounds__(TPB) void mma_gemm(
    const float* __restrict__ A, long Az,
    const float* __restrict__ B, long Bz,
    float* __restrict__ P, int N, int K, int SK,
    const int* __restrict__ patchStart)
{
    const int z = blockIdx.z, s = blockIdx.y;
    const int n0 = blockIdx.x * 64;
    const int kLen = K / SK;
    const int kBeg = s * kLen;
    A += (long)z * Az;
    B += (long)z * Bz + (long)patchStart[z] * DIM;

    __shared__ float Asm[2][96 * 36];
    __shared__ float Bs[2][2304];

    const int tid  = threadIdx.x;
    const int wid  = tid >> 5;
    const int lane = tid & 31;
    const int grp  = lane >> 2;
    const int th   = lane & 3;
    const int warpM = wid >> 2;
    const int warpN = wid & 3;

    auto load_tile = [&](int t, int buf) {
        const int k0 = kBeg + t * 32;
#pragma unroll
        for (int it = 0; it < 3; it++) {
            int idx = tid + it * TPB;
            int m = idx >> 3, kc = idx & 7;
            cp16(&Asm[buf][m * 36 + kc * 4], A + (long)m * K + k0 + kc * 4, true);
        }
        if (TB) {
#pragma unroll
            for (int it = 0; it < 2; it++) {
                int idx = tid + it * TPB;
                int nn = idx >> 3, kc = idx & 7;
                cp16(&Bs[buf][nn * 36 + kc * 4],
                     B + (long)(n0 + nn) * DIM + k0 + kc * 4, true);
            }
        } else {
#pragma unroll
            for (int it = 0; it < 2; it++) {
                int idx = tid + it * TPB;
                int kk = idx >> 4, nc = idx & 15;
                cp16(&Bs[buf][kk * 72 + nc * 4],
                     B + (long)(k0 + kk) * DIM + n0 + nc * 4, true);
            }
        }
        cp_commit();
    };

    float c[3][2][4];
#pragma unroll
    for (int i = 0; i < 3; i++)
#pragma unroll
        for (int j = 0; j < 2; j++)
#pragma unroll
            for (int r = 0; r < 4; r++) c[i][j][r] = 0.f;

    const int nTiles = kLen / 32;
    load_tile(0, 0);
    for (int t = 0; t < nTiles; t++) {
        const int buf = t & 1;
        if (t + 1 < nTiles) { load_tile(t + 1, buf ^ 1); cp_wait<1>(); }
        else                { cp_wait<0>(); }
        __syncthreads();

#pragma unroll
        for (int q = 0; q < 32; q += 8) {
            unsigned a[3][4], b[2][2];
#pragma unroll
            for (int fr = 0; fr < 3; fr++) {
                int row = warpM * 48 + fr * 16 + grp;
                const unsigned* ap  = reinterpret_cast<const unsigned*>(&Asm[buf][row * 36 + q + th]);
                const unsigned* ap8 = reinterpret_cast<const unsigned*>(&Asm[buf][(row + 8) * 36 + q + th]);
                a[fr][0] = ap[0];
                a[fr][1] = ap8[0];
                a[fr][2] = ap[4];
                a[fr][3] = ap8[4];
            }
#pragma unroll
            for (int fn = 0; fn < 2; fn++) {
                int col = warpN * 16 + fn * 8 + grp;
                if (TB) {
                    const unsigned* bp = reinterpret_cast<const unsigned*>(&Bs[buf][col * 36 + q + th]);
                    b[fn][0] = bp[0];
                    b[fn][1] = bp[4];
                } else {
                    b[fn][0] = reinterpret_cast<const unsigned*>(&Bs[buf][(q + th) * 72 + col])[0];
                    b[fn][1] = reinterpret_cast<const unsigned*>(&Bs[buf][(q + th + 4) * 72 + col])[0];
                }
            }
#pragma unroll
            for (int fr = 0; fr < 3; fr++)
#pragma unroll
                for (int fn = 0; fn < 2; fn++) {
                    asm volatile(
                        "mma.sync.aligned.m16n8k8.row.col.f32.tf32.tf32.f32 "
                        "{%0,%1,%2,%3}, {%4,%5,%6,%7}, {%8,%9}, {%0,%1,%2,%3};"
                        : "+f"(c[fr][fn][0]), "+f"(c[fr][fn][1]),
                          "+f"(c[fr][fn][2]), "+f"(c[fr][fn][3])
                        : "r"(a[fr][0]), "r"(a[fr][1]), "r"(a[fr][2]), "r"(a[fr][3]),
                          "r"(b[fn][0]), "r"(b[fn][1]));
                }
        }
        __syncthreads();
    }

    long base = (long)(z * SK + s) * 96 * N;
#pragma unroll
    for (int fr = 0; fr < 3; fr++) {
        int r0 = warpM * 48 + fr * 16 + grp;
#pragma unroll
        for (int fn = 0; fn < 2; fn++) {
            int col = n0 + warpN * 16 + fn * 8 + th * 2;
            *reinterpret_cast<float2*>(&P[base + (long)r0 * N + col]) =
                make_float2(c[fr][fn][0], c[fr][fn][1]);
            *reinterpret_cast<float2*>(&P[base + (long)(r0 + 8) * N + col]) =
                make_float2(c[fr][fn][2], c[fr][fn][3]);
        }
    }
}

// reduce split-K partials + epilogue
__global__ void combine_kernel(const float* __restrict__ P, int SK,
                               float* __restrict__ C, int ldc, long Cz, int M, int N,
                               const float* __restrict__ bias, long biasZ,
                               const float* __restrict__ resid, long residZ,
                               float scale, int act, int total) {
    int idx = blockIdx.x * blockDim.x + threadIdx.x;
    if (idx >= total) return;
    int n = idx % N;
    int t = idx / N;
    int m = t % M;
    int z = t / M;
    float v = 0.f;
    for (int s = 0; s < SK; s++) v += P[((long)(z * SK + s) * M + m) * N + n];
    if (bias)  v += bias[z * biasZ + n];
    v *= scale;
    if (act)   v = v * normcdff(v);
    if (resid) v += resid[z * residZ + (long)m * ldc + n];
    C[z * Cz + (long)m * ldc + n] = v;
}

// ------------------------- masked softmax ------------------------------------
__global__ void softmax_kernel(float* __restrict__ scores,
                               const float* __restrict__ boxes,
                               const int* __restrict__ thw) {
    int blk = blockIdx.x;
    int b = blk / (NBOX * NHD);
    int n = (blk / NHD) % NBOX;
    int hg = thw[1], wg = thw[2];
    const float* bx = boxes + (long)(b * NBOX + n) * 4;
    float x1 = bx[0], y1 = bx[1], x2 = bx[2], y2 = bx[3];
    int px1 = min(max((int)floorf(x1 * (float)wg), 0), wg - 1);
    int px2 = max(px1 + 1, min((int)floorf(x2 * (float)wg), wg));
    int py1 = min(max((int)floorf(y1 * (float)hg), 0), hg - 1);
    int py2 = max(py1 + 1, min((int)floorf(y2 * (float)hg), hg));

    float* row = scores + (long)blk * NPATCH;
    __shared__ float sh[NPATCH];
    __shared__ float red[TPB];
    int tid = threadIdx.x;
    int hw = hg * wg;

    float mx = -1e30f;
    for (int i = tid; i < NPATCH; i += TPB) {
        int q = i % hw;
        int rr = q / wg, cc = q % wg;
        bool in = (rr >= py1) && (rr < py2) && (cc >= px1) && (cc < px2);
        float v = in ? row[i] : -1e30f;
        sh[i] = v;
        mx = fmaxf(mx, v);
    }
    red[tid] = mx;
    __syncthreads();
    for (int s = TPB / 2; s > 0; s >>= 1) {
        if (tid < s) red[tid] = fmaxf(red[tid], red[tid + s]);
        __syncthreads();
    }
    float maxv = red[0];
    __syncthreads();

    float sum = 0.f;
    for (int i = tid; i < NPATCH; i += TPB) {
        float e = expf(sh[i] - maxv);
        sh[i] = e;
        sum += e;
    }
    red[tid] = sum;
    __syncthreads();
    for (int s = TPB / 2; s > 0; s >>= 1) {
        if (tid < s) red[tid] += red[tid + s];
        __syncthreads();
    }
    float inv = 1.f / red[0];
    __syncthreads();
    for (int i = tid; i < NPATCH; i += TPB) row[i] = sh[i] * inv;
}

// ------------------------- layernorm -----------------------------------------
__global__ void ln_kernel(const float* __restrict__ gamma, const float* __restrict__ beta) {
    int r = blockIdx.x;
    const float* x = g_comb + (long)r * DIM;
    __shared__ float red[TPB];
    __shared__ float red2[TPB];
    int tid = threadIdx.x;
    float s = 0.f, s2 = 0.f;
    for (int i = tid; i < DIM; i += TPB) {
        float v = x[i];
        s += v;
        s2 += v * v;
    }
    red[tid] = s; red2[tid] = s2;
    __syncthreads();
    for (int st = TPB / 2; st > 0; st >>= 1) {
        if (tid < st) { red[tid] += red[tid + st]; red2[tid] += red2[tid + st]; }
        __syncthreads();
    }
    float mu = red[0] / DIM;
    float var = red2[0] / DIM - mu * mu;
    float inv = rsqrtf(var + 1e-5f);
    for (int i = tid; i < DIM; i += TPB)
        g_ln[(long)r * DIM + i] = (x[i] - mu) * inv * gamma[i] + beta[i];
}

// ------------------------- launch --------------------------------------------
extern "C" void kernel_launch(void* const* d_in, const int* in_sizes, int n_in,
                              void* d_out, int out_size) {
    const float*         emb   = (const float*)d_in[0];
    const int*           ids   = (const int*)d_in[1];
    const unsigned char* msk   = (const unsigned char*)d_in[2];
    const float*         boxes = (const float*)d_in[3];
    const int*           thw   = (const int*)d_in[4];
    const int*           tok   = (const int*)d_in[5];
    const float*         Win   = (const float*)d_in[6];
    const float*         bin   = (const float*)d_in[7];
    const float*         Wout  = (const float*)d_in[8];
    const float*         bout  = (const float*)d_in[9];
    const float*         gam   = (const float*)d_in[10];
    const float*         bet   = (const float*)d_in[11];
    const float*         W1    = (const float*)d_in[12];
    const float*         b1    = (const float*)d_in[13];
    const float*         W2    = (const float*)d_in[14];
    const float*         b2    = (const float*)d_in[15];
    float*               out   = (float*)d_out;

    const float* Wq = Win;
    const float* Wk = Win + (long)DIM * DIM;
    const float* Wv = Win + 2L * DIM * DIM;
    const float* bv = bin + 2L * DIM;

    float *qtok, *q, *qk, *scores, *u, *ctx, *comb, *ln, *hidden, *rows, *part;
    int *start;
    cudaGetSymbolAddress((void**)&qtok,   g_qtok);
    cudaGetSymbolAddress((void**)&q,      g_q);
    cudaGetSymbolAddress((void**)&qk,     g_qk);
    cudaGetSymbolAddress((void**)&scores, g_scores);
    cudaGetSymbolAddress((void**)&u,      g_u);
    cudaGetSymbolAddress((void**)&ctx,    g_ctx);
    cudaGetSymbolAddress((void**)&comb,   g_comb);
    cudaGetSymbolAddress((void**)&ln,     g_ln);
    cudaGetSymbolAddress((void**)&hidden, g_hidden);
    cudaGetSymbolAddress((void**)&rows,   g_rows);
    cudaGetSymbolAddress((void**)&part,   g_part);
    cudaGetSymbolAddress((void**)&start,  g_start);

    const float scale = 1.0f / sqrtf((float)DHD);
    const long n4 = (long)BATCH * SEQ * DIM / 4;

    // 1. output base copy
    copy_kernel<<<8192, TPB>>>((const float4*)emb, (float4*)out, n4);
    // 2. positions + patch start
    scan_kernel<<<BATCH, TPB>>>(ids, msk, tok);
    // 3. gather query tokens
    gather_kernel<<<NTOK, TPB>>>(emb);

    // 4. q = (qtok @ Wq^T + bq) * scale   (mma TB, SK=16, Kc=224)
    skinny_mma<true><<<dim3(28, 16, 1), TPB>>>(qtok, DIM, 0, Wq, DIM, 0, part, DIM, DIM, 16);
    combine_kernel<<<(NTOK * DIM + TPB - 1) / TPB, TPB>>>(
        part, 16, q, DIM, 0, NTOK, DIM, bin, 0, nullptr, 0, scale, 0, NTOK * DIM);

    // 5. qk[t,h,:] = q[t,h,:] @ Wk_h   (mma NN per head, SK=2, Kc=224)
    skinny_mma<false><<<dim3(28, 2, NHD), TPB>>>(q, DIM, DHD, Wk, DIM, (long)DHD * DIM,
                                                 part, DIM, DHD, 2);
    combine_kernel<<<(NHD * NTOK * DIM + TPB - 1) / TPB, TPB>>>(
        part, 2, qk, NHD * DIM, DIM, NTOK, DIM, nullptr, 0, nullptr, 0, 1.f, 0,
        NHD * NTOK * DIM);

    // 6. scores = qk @ patches^T   (tf32 mma, SK=4)
    mma_gemm<true><<<dim3(NPATCH / 64, 4, BATCH), TPB>>>(
        qk, (long)96 * DIM, emb, (long)SEQ * DIM,
        part, NPATCH, DIM, 4, start);
    combine_kernel<<<(BATCH * 96 * NPATCH + TPB - 1) / TPB, TPB>>>(
        part, 4, scores, NPATCH, (long)96 * NPATCH, 96, NPATCH,
        nullptr, 0, nullptr, 0, 1.f, 0, BATCH * 96 * NPATCH);

    // 7. masked softmax
    softmax_kernel<<<BATCH * NBOX * NHD, TPB>>>(scores, boxes, thw);

    // 8. u = attn @ patches   (tf32 mma, SK=4)
    mma_gemm<false><<<dim3(DIM / 64, 4, BATCH), TPB>>>(
        scores, (long)96 * NPATCH, emb, (long)SEQ * DIM,
        part, DIM, NPATCH, 4, start);
    combine_kernel<<<(BATCH * 96 * DIM + TPB - 1) / TPB, TPB>>>(
        part, 4, u, DIM, (long)96 * DIM, 96, DIM,
        nullptr, 0, nullptr, 0, 1.f, 0, BATCH * 96 * DIM);

    // 9. ctx[:, h] = u_h @ Wv_h^T + bv_h   (mma TB per head, SK=16)
    skinny_mma<true><<<dim3(4, 16, NHD), TPB>>>(u, NHD * DIM, DIM, Wv, DIM, (long)DHD * DIM,
                                                part, DHD, DIM, 16);
    combine_kernel<<<(NHD * NTOK * DHD + TPB - 1) / TPB, TPB>>>(
        part, 16, ctx, DIM, DHD, NTOK, DHD, bv, DHD, nullptr, 0, 1.f, 0,
        NHD * NTOK * DHD);

    // 10. combined = ctx @ Wout^T + bout + qtok   (mma TB, SK=16)
    skinny_mma<true><<<dim3(28, 16, 1), TPB>>>(ctx, DIM, 0, Wout, DIM, 0, part, DIM, DIM, 16);
    combine_kernel<<<(NTOK * DIM + TPB - 1) / TPB, TPB>>>(
        part, 16, comb, DIM, 0, NTOK, DIM, bout, 0, qtok, 0, 1.f, 0, NTOK * DIM);

    // 11. layernorm
    ln_kernel<<<NTOK, TPB>>>(gam, bet);

    // 12. hidden = gelu(ln @ W1^T + b1)   (mma TB, SK=8, Kc=448)
    skinny_mma<true><<<dim3(56, 8, 1), TPB>>>(ln, DIM, 0, W1, DIM, 0, part, DFF, DIM, 8);
    combine_kernel<<<(NTOK * DFF + TPB - 1) / TPB, TPB>>>(
        part, 8, hidden, DFF, 0, NTOK, DFF, b1, 0, nullptr, 0, 1.f, 1, NTOK * DFF);

    // 13. rows = ln + hidden @ W2^T + b2   (mma TB, SK=16, Kc=448)
    skinny_mma<true><<<dim3(28, 16, 1), TPB>>>(hidden, DFF, 0, W2, DFF, 0, part, DIM, DFF, 16);
    combine_kernel<<<(NTOK * DIM + TPB - 1) / TPB, TPB>>>(
        part, 16, rows, DIM, 0, NTOK, DIM, b2, 0, ln, 0, 1.f, 0, NTOK * DIM);

    // 14. scatter
    scatter_kernel<<<NTOK, TPB>>>(out);
}

// round 8
// speedup vs baseline: 3.3957x; 1.0135x over previous
#include <cuda_runtime.h>
#include <math.h>

#define BATCH   2
#define SEQ     4608
#define DIM     3584
#define NHD     8
#define DHD     448
#define NPATCH  4096
#define NBOX    12
#define DFF     7168
#define NTOK    24
#define TPB     256

#define STG     5760        // floats per pipeline stage (both mma kernels)
#define SMEM_BYTES (3 * STG * 4)

// ------------------------- scratch ------------------------------------------
__device__ int   g_pos[NTOK];
__device__ int   g_start[BATCH];
__device__ float g_qtok[NTOK * DIM];
__device__ float g_q[NTOK * DIM];
__device__ float g_qk[NTOK * NHD * DIM];
__device__ float g_scores[BATCH * NBOX * NHD * NPATCH];
__device__ float g_u[NTOK * NHD * DIM];
__device__ float g_ctx[NTOK * DIM];
__device__ float g_comb[NTOK * DIM];
__device__ float g_ln[NTOK * DIM];
__device__ float g_hidden[NTOK * DFF];
__device__ float g_rows[NTOK * DIM];
__device__ float g_part[5505024];          // split-K partial scratch (22 MB)

// ------------------------- cp.async helpers ----------------------------------
__device__ __forceinline__ void cp16(void* smem, const void* gmem, bool pred) {
    unsigned sa = (unsigned)__cvta_generic_to_shared(smem);
    int sz = pred ? 16 : 0;
    asm volatile("cp.async.cg.shared.global [%0], [%1], 16, %2;\n"
                 :: "r"(sa), "l"(gmem), "r"(sz));
}
__device__ __forceinline__ void cp_commit() {
    asm volatile("cp.async.commit_group;\n");
}
template<int NWAIT>
__device__ __forceinline__ void cp_wait() {
    asm volatile("cp.async.wait_group %0;\n" :: "n"(NWAIT));
}

// ------------------------- simple kernels ------------------------------------
__global__ void copy_kernel(const float4* __restrict__ src, float4* __restrict__ dst, long n4) {
    long i = (long)blockIdx.x * blockDim.x + threadIdx.x;
    long stride = (long)gridDim.x * blockDim.x;
    for (; i < n4; i += stride) dst[i] = src[i];
}

__global__ void scan_kernel(const int* __restrict__ ids,
                            const unsigned char* __restrict__ mask,
                            const int* __restrict__ tokPtr) {
    int b = blockIdx.x;
    __shared__ int sh[SEQ];
    __shared__ int s_f0, s_es, s_off, s_first;
    int tid = threadIdx.x;

    if (tid == 0) s_f0 = 0x7fffffff;
    __syncthreads();
    for (int i = tid; i < SEQ; i += blockDim.x) {
        if (mask[i] != 0) { atomicMin(&s_f0, i); break; }
    }
    __syncthreads();
    if (tid == 0) {
        int f0 = s_f0;
        unsigned char b0 = mask[f0];
        unsigned char b1 = mask[f0 + 1];
        if (b0 == 1u && b1 == 0u)      { s_es = 4; s_off = 0; }
        else if (b0 == 0x80u)          { s_es = 4; s_off = 2; }
        else                           { s_es = 1; s_off = 0; }
        s_first = SEQ;
    }
    __syncthreads();
    int es = s_es, off = s_off;
    for (int i = tid; i < SEQ; i += blockDim.x)
        if (mask[((long)b * SEQ + i) * es + off] != 0) atomicMin(&s_first, i);
    __syncthreads();
    if (tid == 0) g_start[b] = s_first;

    for (int i = tid; i < SEQ; i += blockDim.x)
        sh[i] = ids[(long)b * SEQ + i];
    __syncthreads();
    if (tid < 32) {
        int tok = *tokPtr;
        int count = 0;
        for (int base = 0; base < SEQ && count < NBOX; base += 32) {
            unsigned bal = __ballot_sync(0xffffffffu, sh[base + tid] == tok);
            while (bal && count < NBOX) {
                int o = __ffs(bal) - 1;
                if (tid == 0) g_pos[b * NBOX + count] = base + o;
                count++;
                bal &= bal - 1;
            }
        }
    }
}

__global__ void gather_kernel(const float* __restrict__ emb) {
    int r = blockIdx.x;
    int b = r / NBOX;
    const float* src = emb + ((long)b * SEQ + g_pos[r]) * DIM;
    for (int i = threadIdx.x; i < DIM; i += blockDim.x) g_qtok[(long)r * DIM + i] = src[i];
}

__global__ void scatter_kernel(float* __restrict__ out) {
    int r = blockIdx.x;
    int b = r / NBOX;
    float* dst = out + ((long)b * SEQ + g_pos[r]) * DIM;
    for (int i = threadIdx.x; i < DIM; i += blockDim.x) dst[i] = g_rows[(long)r * DIM + i];
}

// ------------------------- skinny tf32 mma GEMM (3-stage pipeline) -----------
// C[24,N] = A[24,K] @ (TB ? W[n,k]^T : W[k,n]).  M padded to 32 with zeros.
// BM=32, BN=128, BK=32. 8 warps each m32 x n16. Split-K partials.
template<bool TB>
__global__ __launch_bounds__(TPB) void skinny_mma(
    const float* __restrict__ A, int lda, long Az,
    const float* __restrict__ W, int ldw, long Wz,
    float* __restrict__ P, int N, int K, int SK)
{
    extern __shared__ float smem[];
    const int z = blockIdx.z, s = blockIdx.y;
    const int n0 = blockIdx.x * 128;
    const int Kc = K / SK;
    const int kBeg = s * Kc;
    A += (long)z * Az;
    W += (long)z * Wz;

    const int tid  = threadIdx.x;
    const int wid  = tid >> 5;
    const int lane = tid & 31;
    const int grp  = lane >> 2;
    const int th   = lane & 3;

    const int am = tid >> 3, akc = tid & 7;

    auto load_tile = [&](int t, int buf) {
        float* As = smem + buf * STG;          // 32*36 floats
        float* Bp = smem + buf * STG + 1152;   // 128*36 (TB) / 32*136 (NN) floats
        const int k0 = kBeg + t * 32;
        cp16(&As[am * 36 + akc * 4], A + (long)am * lda + k0 + akc * 4, am < NTOK);
        if (TB) {
#pragma unroll
            for (int it = 0; it < 4; it++) {
                int idx = tid + it * TPB;
                int nn = idx >> 3, kc = idx & 7;
                cp16(&Bp[nn * 36 + kc * 4],
                     W + (long)(n0 + nn) * ldw + k0 + kc * 4, n0 + nn < N);
            }
        } else {
#pragma unroll
            for (int it = 0; it < 4; it++) {
                int idx = tid + it * TPB;
                int kk = idx >> 5, nc = idx & 31;
                cp16(&Bp[kk * 136 + nc * 4],
                     W + (long)(k0 + kk) * ldw + n0 + nc * 4, n0 + nc * 4 < N);
            }
        }
        cp_commit();
    };

    float c[2][2][4];
#pragma unroll
    for (int i = 0; i < 2; i++)
#pragma unroll
        for (int j = 0; j < 2; j++)
#pragma unroll
            for (int r = 0; r < 4; r++) c[i][j][r] = 0.f;

    const int nT = Kc / 32;
    load_tile(0, 0);
    if (nT > 1) load_tile(1, 1);
    for (int t = 0; t < nT; t++) {
        const int buf = t % 3;
        if (t + 2 < nT) load_tile(t + 2, (t + 2) % 3);
        int ahead = nT - 1 - t;
        if (ahead >= 2)      cp_wait<2>();
        else if (ahead == 1) cp_wait<1>();
        else                 cp_wait<0>();
        __syncthreads();

        const float* As = smem + buf * STG;
        const float* Bp = smem + buf * STG + 1152;

#pragma unroll
        for (int q = 0; q < 32; q += 8) {
            unsigned a[2][4], b[2][2];
#pragma unroll
            for (int mt = 0; mt < 2; mt++) {
                int row = mt * 16 + grp;
                const unsigned* ap  = reinterpret_cast<const unsigned*>(&As[row * 36 + q + th]);
                const unsigned* ap8 = reinterpret_cast<const unsigned*>(&As[(row + 8) * 36 + q + th]);
                a[mt][0] = ap[0];
                a[mt][1] = ap8[0];
                a[mt][2] = ap[4];
                a[mt][3] = ap8[4];
            }
#pragma unroll
            for (int fn = 0; fn < 2; fn++) {
                int col = wid * 16 + fn * 8 + grp;
                if (TB) {
                    const unsigned* bp = reinterpret_cast<const unsigned*>(&Bp[col * 36 + q + th]);
                    b[fn][0] = bp[0];
                    b[fn][1] = bp[4];
                } else {
                    b[fn][0] = reinterpret_cast<const unsigned*>(&Bp[(q + th) * 136 + col])[0];
                    b[fn][1] = reinterpret_cast<const unsigned*>(&Bp[(q + th + 4) * 136 + col])[0];
                }
            }
#pragma unroll
            for (int mt = 0; mt < 2; mt++)
#pragma unroll
                for (int fn = 0; fn < 2; fn++) {
                    asm volatile(
                        "mma.sync.aligned.m16n8k8.row.col.f32.tf32.tf32.f32 "
                        "{%0,%1,%2,%3}, {%4,%5,%6,%7}, {%8,%9}, {%0,%1,%2,%3};"
                        : "+f"(c[mt][fn][0]), "+f"(c[mt][fn][1]),
                          "+f"(c[mt][fn][2]), "+f"(c[mt][fn][3])
                        : "r"(a[mt][0]), "r"(a[mt][1]), "r"(a[mt][2]), "r"(a[mt][3]),
                          "r"(b[fn][0]), "r"(b[fn][1]));
                }
        }
        __syncthreads();
    }

    long base = (long)(z * SK + s) * NTOK * N;
#pragma unroll
    for (int mt = 0; mt < 2; mt++) {
        int r0 = mt * 16 + grp;
#pragma unroll
        for (int fn = 0; fn < 2; fn++) {
            int col = n0 + wid * 16 + fn * 8 + th * 2;
            if (col < N) {
                *reinterpret_cast<float2*>(&P[base + (long)r0 * N + col]) =
                    make_float2(c[mt][fn][0], c[mt][fn][1]);
                if (mt == 0)
                    *reinterpret_cast<float2*>(&P[base + (long)(r0 + 8) * N + col]) =
                        make_float2(c[mt][fn][2], c[mt][fn][3]);
            }
        }
    }
}

// ------------------------- big tf32 mma GEMM (M=96, 3-stage pipeline) --------
template<bool TB>
__global__ __launch_bounds__(TPB) void mma_gemm(
    const float* __restrict__ A, long Az,
    const float* __restrict__ B, long Bz,
    float* __restrict__ P, int N, int K, int SK,
    const int* __restrict__ patchStart)
{
    extern __shared__ float smem[];
    const int z = blockIdx.z, s = blockIdx.y;
    const int n0 = blockIdx.x * 64;
    const int kLen = K / SK;
    const int kBeg = s * kLen;
    A += (long)z * Az;
    B += (long)z * Bz + (long)patchStart[z] * DIM;

    const int tid  = threadIdx.x;
    const int wid  = tid >> 5;
    const int lane = tid & 31;
    const int grp  = lane >> 2;
    const int th   = lane & 3;
    const int warpM = wid >> 2;
    const int warpN = wid & 3;

    auto load_tile = [&](int t, int buf) {
        float* As = smem + buf * STG;          // 96*36 floats
        float* Bp = smem + buf * STG + 3456;   // 2304 floats
        const int k0 = kBeg + t * 32;
#pragma unroll
        for (int it = 0; it < 3; it++) {
            int idx = tid + it * TPB;
            int m = idx >> 3, kc = idx & 7;
            cp16(&As[m * 36 + kc * 4], A + (long)m * K + k0 + kc * 4, true);
        }
        if (TB) {
#pragma unroll
            for (int it = 0; it < 2; it++) {
                int idx = tid + it * TPB;
                int nn = idx >> 3, kc = idx & 7;
                cp16(&Bp[nn * 36 + kc * 4], B + (long)(n0 + nn) * DIM + k0 + kc * 4, true);
            }
        } else {
#pragma unroll
            for (int it = 0; it < 2; it++) {
                int idx = tid + it * TPB;
                int kk = idx >> 4, nc = idx & 15;
                cp16(&Bp[kk * 72 + nc * 4], B + (long)(k0 + kk) * DIM + n0 + nc * 4, true);
            }
        }
        cp_commit();
    };

    float c[3][2][4];
#pragma unroll
    for (int i = 0; i < 3; i++)
#pragma unroll
        for (int j = 0; j < 2; j++)
#pragma unroll
            for (int r = 0; r < 4; r++) c[i][j][r] = 0.f;

    const int nT = kLen / 32;
    load_tile(0, 0);
    if (nT > 1) load_tile(1, 1);
    for (int t = 0; t < nT; t++) {
        const int buf = t % 3;
        if (t + 2 < nT) load_tile(t + 2, (t + 2) % 3);
        int ahead = nT - 1 - t;
        if (ahead >= 2)      cp_wait<2>();
        else if (ahead == 1) cp_wait<1>();
        else                 cp_wait<0>();
        __syncthreads();

        const float* As = smem + buf * STG;
        const float* Bp = smem + buf * STG + 3456;

#pragma unroll
        for (int q = 0; q < 32; q += 8) {
            unsigned a[3][4], b[2][2];
#pragma unroll
            for (int fr = 0; fr < 3; fr++) {
                int row = warpM * 48 + fr * 16 + grp;
                const unsigned* ap  = reinterpret_cast<const unsigned*>(&As[row * 36 + q + th]);
                const unsigned* ap8 = reinterpret_cast<const unsigned*>(&As[(row + 8) * 36 + q + th]);
                a[fr][0] = ap[0];
                a[fr][1] = ap8[0];
                a[fr][2] = ap[4];
                a[fr][3] = ap8[4];
            }
#pragma unroll
            for (int fn = 0; fn < 2; fn++) {
                int col = warpN * 16 + fn * 8 + grp;
                if (TB) {
                    const unsigned* bp = reinterpret_cast<const unsigned*>(&Bp[col * 36 + q + th]);
                    b[fn][0] = bp[0];
                    b[fn][1] = bp[4];
                } else {
                    b[fn][0] = reinterpret_cast<const unsigned*>(&Bp[(q + th) * 72 + col])[0];
                    b[fn][1] = reinterpret_cast<const unsigned*>(&Bp[(q + th + 4) * 72 + col])[0];
                }
            }
#pragma unroll
            for (int fr = 0; fr < 3; fr++)
#pragma unroll
                for (int fn = 0; fn < 2; fn++) {
                    asm volatile(
                        "mma.sync.aligned.m16n8k8.row.col.f32.tf32.tf32.f32 "
                        "{%0,%1,%2,%3}, {%4,%5,%6,%7}, {%8,%9}, {%0,%1,%2,%3};"
                        : "+f"(c[fr][fn][0]), "+f"(c[fr][fn][1]),
                          "+f"(c[fr][fn][2]), "+f"(c[fr][fn][3])
                        : "r"(a[fr][0]), "r"(a[fr][1]), "r"(a[fr][2]), "r"(a[fr][3]),
                          "r"(b[fn][0]), "r"(b[fn][1]));
                }
        }
        __syncthreads();
    }

    long base = (long)(z * SK + s) * 96 * N;
#pragma unroll
    for (int fr = 0; fr < 3; fr++) {
        int r0 = warpM * 48 + fr * 16 + grp;
#pragma unroll
        for (int fn = 0; fn < 2; fn++) {
            int col = n0 + warpN * 16 + fn * 8 + th * 2;
            *reinterpret_cast<float2*>(&P[base + (long)r0 * N + col]) =
                make_float2(c[fr][fn][0], c[fr][fn][1]);
            *reinterpret_cast<float2*>(&P[base + (long)(r0 + 8) * N + col]) =
                make_float2(c[fr][fn][2], c[fr][fn][3]);
        }
    }
}

// reduce split-K partials + epilogue
__global__ void combine_kernel(const float* __restrict__ P, int SK,
                               float* __restrict__ C, int ldc, long Cz, int M, int N,
                               const float* __restrict__ bias, long biasZ,
                               const float* __restrict__ resid, long residZ,
                               float scale, int act, int total) {
    int idx = blockIdx.x * blockDim.x + threadIdx.x;
    if (idx >= total) return;
    int n = idx % N;
    int t = idx / N;
    int m = t % M;
    int z = t / M;
    float v = 0.f;
    for (int s = 0; s < SK; s++) v += P[((long)(z * SK + s) * M + m) * N + n];
    if (bias)  v += bias[z * biasZ + n];
    v *= scale;
    if (act)   v = v * normcdff(v);
    if (resid) v += resid[z * residZ + (long)m * ldc + n];
    C[z * Cz + (long)m * ldc + n] = v;
}

// ------------------------- masked softmax (fuses score split-K reduce) -------
__global__ void softmax_kernel(const float* __restrict__ P,   // score partials, SK=4
                               float* __restrict__ attn,
                               const float* __restrict__ boxes,
                               const int* __restrict__ thw) {
    int blk = blockIdx.x;
    int b = blk / (NBOX * NHD);
    int n = (blk / NHD) % NBOX;
    int h = blk % NHD;
    int m = n * NHD + h;
    int hg = thw[1], wg = thw[2];
    const float* bx = boxes + (long)(b * NBOX + n) * 4;
    float x1 = bx[0], y1 = bx[1], x2 = bx[2], y2 = bx[3];
    int px1 = min(max((int)floorf(x1 * (float)wg), 0), wg - 1);
    int px2 = max(px1 + 1, min((int)floorf(x2 * (float)wg), wg));
    int py1 = min(max((int)floorf(y1 * (float)hg), 0), hg - 1);
    int py2 = max(py1 + 1, min((int)floorf(y2 * (float)hg), hg));

    const float* r0 = P + ((long)(b * 4 + 0) * 96 + m) * NPATCH;
    const float* r1 = P + ((long)(b * 4 + 1) * 96 + m) * NPATCH;
    const float* r2 = P + ((long)(b * 4 + 2) * 96 + m) * NPATCH;
    const float* r3 = P + ((long)(b * 4 + 3) * 96 + m) * NPATCH;
    float* orow = attn + (long)blk * NPATCH;

    __shared__ float sh[NPATCH];
    __shared__ float red[TPB];
    int tid = threadIdx.x;
    int hw = hg * wg;

    float mx = -1e30f;
    for (int i = tid; i < NPATCH; i += TPB) {
        int q = i % hw;
        int rr = q / wg, cc = q % wg;
        bool in = (rr >= py1) && (rr < py2) && (cc >= px1) && (cc < px2);
        float v = in ? (r0[i] + r1[i] + r2[i] + r3[i]) : -1e30f;
        sh[i] = v;
        mx = fmaxf(mx, v);
    }
    red[tid] = mx;
    __syncthreads();
    for (int s = TPB / 2; s > 0; s >>= 1) {
        if (tid < s) red[tid] = fmaxf(red[tid], red[tid + s]);
        __syncthreads();
    }
    float maxv = red[0];
    __syncthreads();

    float sum = 0.f;
    for (int i = tid; i < NPATCH; i += TPB) {
        float e = expf(sh[i] - maxv);
        sh[i] = e;
        sum += e;
    }
    red[tid] = sum;
    __syncthreads();
    for (int s = TPB / 2; s > 0; s >>= 1) {
        if (tid < s) red[tid] += red[tid + s];
        __syncthreads();
    }
    float inv = 1.f / red[0];
    __syncthreads();
    for (int i = tid; i < NPATCH; i += TPB) orow[i] = sh[i] * inv;
}

// ------------------------- layernorm (fuses combined split-K reduce) ---------
// combined = sum_{s<16} P[(s*24+r)*DIM+i] + bout[i] + qtok[r*DIM+i]; then LN.
__global__ void ln_fused_kernel(const float* __restrict__ P,
                                const float* __restrict__ bout,
                                const float* __restrict__ gamma,
                                const float* __restrict__ beta) {
    int r = blockIdx.x;
    __shared__ float red[TPB];
    __shared__ float red2[TPB];
    int tid = threadIdx.x;
    float s = 0.f, s2 = 0.f;
    for (int i = tid; i < DIM; i += TPB) {
        float v = bout[i] + g_qtok[(long)r * DIM + i];
#pragma unroll
        for (int k = 0; k < 16; k++)
            v += P[((long)(k * NTOK) + r) * DIM + i];
        g_comb[(long)r * DIM + i] = v;
        s += v;
        s2 += v * v;
    }
    red[tid] = s; red2[tid] = s2;
    __syncthreads();
    for (int st = TPB / 2; st > 0; st >>= 1) {
        if (tid < st) { red[tid] += red[tid + st]; red2[tid] += red2[tid + st]; }
        __syncthreads();
    }
    float mu = red[0] / DIM;
    float var = red2[0] / DIM - mu * mu;
    float inv = rsqrtf(var + 1e-5f);
    for (int i = tid; i < DIM; i += TPB)
        g_ln[(long)r * DIM + i] = (g_comb[(long)r * DIM + i] - mu) * inv * gamma[i] + beta[i];
}

// ------------------------- launch --------------------------------------------
extern "C" void kernel_launch(void* const* d_in, const int* in_sizes, int n_in,
                              void* d_out, int out_size) {
    const float*         emb   = (const float*)d_in[0];
    const int*           ids   = (const int*)d_in[1];
    const unsigned char* msk   = (const unsigned char*)d_in[2];
    const float*         boxes = (const float*)d_in[3];
    const int*           thw   = (const int*)d_in[4];
    const int*           tok   = (const int*)d_in[5];
    const float*         Win   = (const float*)d_in[6];
    const float*         bin   = (const float*)d_in[7];
    const float*         Wout  = (const float*)d_in[8];
    const float*         bout  = (const float*)d_in[9];
    const float*         gam   = (const float*)d_in[10];
    const float*         bet   = (const float*)d_in[11];
    const float*         W1    = (const float*)d_in[12];
    const float*         b1    = (const float*)d_in[13];
    const float*         W2    = (const float*)d_in[14];
    const float*         b2    = (const float*)d_in[15];
    float*               out   = (float*)d_out;

    const float* Wq = Win;
    const float* Wk = Win + (long)DIM * DIM;
    const float* Wv = Win + 2L * DIM * DIM;
    const float* bv = bin + 2L * DIM;

    float *qtok, *q, *qk, *scores, *u, *ctx, *ln, *hidden, *rows, *part;
    int *start;
    cudaGetSymbolAddress((void**)&qtok,   g_qtok);
    cudaGetSymbolAddress((void**)&q,      g_q);
    cudaGetSymbolAddress((void**)&qk,     g_qk);
    cudaGetSymbolAddress((void**)&scores, g_scores);
    cudaGetSymbolAddress((void**)&u,      g_u);
    cudaGetSymbolAddress((void**)&ctx,    g_ctx);
    cudaGetSymbolAddress((void**)&ln,     g_ln);
    cudaGetSymbolAddress((void**)&hidden, g_hidden);
    cudaGetSymbolAddress((void**)&rows,   g_rows);
    cudaGetSymbolAddress((void**)&part,   g_part);
    cudaGetSymbolAddress((void**)&start,  g_start);

    cudaFuncSetAttribute(skinny_mma<true>,  cudaFuncAttributeMaxDynamicSharedMemorySize, SMEM_BYTES);
    cudaFuncSetAttribute(skinny_mma<false>, cudaFuncAttributeMaxDynamicSharedMemorySize, SMEM_BYTES);
    cudaFuncSetAttribute(mma_gemm<true>,    cudaFuncAttributeMaxDynamicSharedMemorySize, SMEM_BYTES);
    cudaFuncSetAttribute(mma_gemm<false>,   cudaFuncAttributeMaxDynamicSharedMemorySize, SMEM_BYTES);

    const float scale = 1.0f / sqrtf((float)DHD);
    const long n4 = (long)BATCH * SEQ * DIM / 4;

    // ---- fork: base copy runs concurrently on a side stream ----
    cudaStream_t s2;
    cudaStreamCreate(&s2);
    cudaEvent_t eFork, eJoin;
    cudaEventCreateWithFlags(&eFork, cudaEventDisableTiming);
    cudaEventCreateWithFlags(&eJoin, cudaEventDisableTiming);
    cudaEventRecord(eFork, 0);
    cudaStreamWaitEvent(s2, eFork, 0);
    copy_kernel<<<8192, TPB, 0, s2>>>((const float4*)emb, (float4*)out, n4);
    cudaEventRecord(eJoin, s2);

    // ---- main chain on default stream ----
    scan_kernel<<<BATCH, TPB>>>(ids, msk, tok);
    gather_kernel<<<NTOK, TPB>>>(emb);

    // 4. q = (qtok @ Wq^T + bq) * scale   (SK=16, Kc=224)
    skinny_mma<true><<<dim3(28, 16, 1), TPB, SMEM_BYTES>>>(qtok, DIM, 0, Wq, DIM, 0, part, DIM, DIM, 16);
    combine_kernel<<<(NTOK * DIM + TPB - 1) / TPB, TPB>>>(
        part, 16, q, DIM, 0, NTOK, DIM, bin, 0, nullptr, 0, scale, 0, NTOK * DIM);

    // 5. qk[t,h,:] = q[t,h,:] @ Wk_h   (NN per head, SK=2, Kc=224)
    skinny_mma<false><<<dim3(28, 2, NHD), TPB, SMEM_BYTES>>>(q, DIM, DHD, Wk, DIM, (long)DHD * DIM,
                                                             part, DIM, DHD, 2);
    combine_kernel<<<(NHD * NTOK * DIM + TPB - 1) / TPB, TPB>>>(
        part, 2, qk, NHD * DIM, DIM, NTOK, DIM, nullptr, 0, nullptr, 0, 1.f, 0,
        NHD * NTOK * DIM);

    // 6. scores = qk @ patches^T   (SK=4) -> partials consumed by softmax
    mma_gemm<true><<<dim3(NPATCH / 64, 4, BATCH), TPB, SMEM_BYTES>>>(
        qk, (long)96 * DIM, emb, (long)SEQ * DIM,
        part, NPATCH, DIM, 4, start);

    // 7. masked softmax (reduces 4 partials in-kernel)
    softmax_kernel<<<BATCH * NBOX * NHD, TPB>>>(part, scores, boxes, thw);

    // 8. u = attn @ patches   (SK=4)
    mma_gemm<false><<<dim3(DIM / 64, 4, BATCH), TPB, SMEM_BYTES>>>(
        scores, (long)96 * NPATCH, emb, (long)SEQ * DIM,
        part, DIM, NPATCH, 4, start);
    combine_kernel<<<(BATCH * 96 * DIM + TPB - 1) / TPB, TPB>>>(
        part, 4, u, DIM, (long)96 * DIM, 96, DIM,
        nullptr, 0, nullptr, 0, 1.f, 0, BATCH * 96 * DIM);

    // 9. ctx[:, h] = u_h @ Wv_h^T + bv_h   (SK=16)
    skinny_mma<true><<<dim3(4, 16, NHD), TPB, SMEM_BYTES>>>(u, NHD * DIM, DIM, Wv, DIM, (long)DHD * DIM,
                                                            part, DHD, DIM, 16);
    combine_kernel<<<(NHD * NTOK * DHD + TPB - 1) / TPB, TPB>>>(
        part, 16, ctx, DIM, DHD, NTOK, DHD, bv, DHD, nullptr, 0, 1.f, 0,
        NHD * NTOK * DHD);

    // 10. combined partials = ctx @ Wout^T   (SK=16) -> consumed by ln_fused
    skinny_mma<true><<<dim3(28, 16, 1), TPB, SMEM_BYTES>>>(ctx, DIM, 0, Wout, DIM, 0, part, DIM, DIM, 16);

    // 11. layernorm (reduces 16 partials + bout + qtok residual in-kernel)
    ln_fused_kernel<<<NTOK, TPB>>>(part, bout, gam, bet);

    // 12. hidden = gelu(ln @ W1^T + b1)   (SK=8, Kc=448)
    skinny_mma<true><<<dim3(56, 8, 1), TPB, SMEM_BYTES>>>(ln, DIM, 0, W1, DIM, 0, part, DFF, DIM, 8);
    combine_kernel<<<(NTOK * DFF + TPB - 1) / TPB, TPB>>>(
        part, 8, hidden, DFF, 0, NTOK, DFF, b1, 0, nullptr, 0, 1.f, 1, NTOK * DFF);

    // 13. rows = ln + hidden @ W2^T + b2   (SK=16, Kc=448)
    skinny_mma<true><<<dim3(28, 16, 1), TPB, SMEM_BYTES>>>(hidden, DFF, 0, W2, DFF, 0, part, DIM, DFF, 16);
    combine_kernel<<<(NTOK * DIM + TPB - 1) / TPB, TPB>>>(
        part, 16, rows, DIM, 0, NTOK, DIM, b2, 0, ln, 0, 1.f, 0, NTOK * DIM);

    // ---- join: copy must be done before scatter ----
    cudaStreamWaitEvent(0, eJoin, 0);
    scatter_kernel<<<NTOK, TPB>>>(out);
}